// round 13
// baseline (speedup 1.0000x reference)
#include <cuda_runtime.h>
#include <cstdint>

#define Bn 2
#define Nn 2048
#define Kn 256
#define Dn 768
#define Hn 256
#define Ln 64
#define BND (Bn*Nn*Dn)
#define BKD (Bn*Kn*Dn)
#define BKH (Bn*Kn*Hn)
#define BKKL ((size_t)Bn*Kn*Kn*Ln)

// ---------------- scratch (device globals; no allocations allowed) ----------
__device__ float g_left [BKH];
__device__ float g_right[BKH];
__device__ float g_outwT[Hn*Ln];      // [h][l], tf32-rounded
__device__ float g_AwT  [Ln*Dn];      // [l][d], tf32-rounded
__device__ float g_BwT  [Ln*Dn];      // [l][d], tf32-rounded
__device__ float g_probs[BKKL];       // sigmoid(score)*mask, tf32-rounded
__device__ float g_part [16][BKD];    // ctxt partials 0..5; proj 0..2; gate 6..9
__device__ float g_c    [BKD];

__device__ __forceinline__ float sigmoidf(float x) {
    return 1.0f / (1.0f + __expf(-x));
}
__device__ __forceinline__ uint32_t tf32r(float x) {
    uint32_t u; asm("cvt.rna.tf32.f32 %0, %1;" : "=r"(u) : "f"(x)); return u;
}
__device__ __forceinline__ float tf32rf(float x) {
    return __uint_as_float(tf32r(x));
}
__device__ __forceinline__ void mma8(float c[4], uint32_t a0, uint32_t a1, uint32_t a2,
                                     uint32_t a3, uint32_t b0, uint32_t b1) {
    asm("mma.sync.aligned.m16n8k8.row.col.f32.tf32.tf32.f32 "
        "{%0,%1,%2,%3},{%4,%5,%6,%7},{%8,%9},{%0,%1,%2,%3};"
        : "+f"(c[0]), "+f"(c[1]), "+f"(c[2]), "+f"(c[3])
        : "r"(a0), "r"(a1), "r"(a2), "r"(a3), "r"(b0), "r"(b1));
}
__device__ __forceinline__ void cp16(uint32_t daddr, const void* src) {
    asm volatile("cp.async.cg.shared.global [%0], [%1], 16;\n" :: "r"(daddr), "l"(src));
}

// ---------------- prep: tf32-rounded weight transposes ---------------------
__global__ void prep_kernel(const float* __restrict__ out_w,
                            const float* __restrict__ A_w,
                            const float* __restrict__ B_w) {
    int i = blockIdx.x * blockDim.x + threadIdx.x;
    if (i < Hn * Ln) { int h = i / Ln, l = i - h * Ln; g_outwT[i] = tf32rf(out_w[l * Hn + h]); }
    if (i < Ln * Dn) { int l = i / Dn, d = i - l * Dn; g_AwT[i] = tf32rf(A_w[d * Ln + l]);
                                                      g_BwT[i] = tf32rf(B_w[d * Ln + l]); }
}

// 4 float4 per thread (MLP=4)
__global__ void copy_init_kernel(const float* __restrict__ all_vecs,
                                 const float* __restrict__ span_vecs,
                                 float* __restrict__ outAll,
                                 float* __restrict__ outU) {
    const int stride = BND / 16;   // 196608 threads cover BND/4 float4s in 4 passes
    int i = blockIdx.x * blockDim.x + threadIdx.x;
    if (i < stride) {
#pragma unroll
        for (int e = 0; e < 4; e++) {
            int idx = i + e * stride;
            ((float4*)outAll)[idx] = ((const float4*)all_vecs)[idx];
        }
        if (i < BKD / 4) ((float4*)outU)[i] = ((const float4*)span_vecs)[i];
    }
}

// ---------------- proj split-K: partials for u @ [left_w|right_w]^T --------
// grid (4, 8, 3): m-tile 128, n-tile 64 over 512 cols, split z covers k [z*256,(z+1)*256)
__global__ __launch_bounds__(256) void proj_kernel(const float* __restrict__ u,
        const float* __restrict__ left_w, const float* __restrict__ right_w) {
    __shared__ float As[128][36];
    const int tid = threadIdx.x;
    const int warp = tid >> 5, lane = tid & 31;
    const int wm = warp & 3, wn = warp >> 2;
    const int grp = lane >> 2, q = lane & 3;
    const int m0 = blockIdx.x * 128, n0 = blockIdx.y * 64;
    const int kBeg = blockIdx.z * 256, kEnd = kBeg + 256;
    const bool isL = (n0 < Hn);
    const float* W = isL ? left_w : right_w;
    const int nloc0 = isL ? n0 : n0 - Hn;
    const int fm = tid >> 1, fh = tid & 1;
    float acc[2][4][4] = {};

    for (int kb = kBeg; kb < kEnd; kb += 32) {
        const float* src = u + (size_t)(m0 + fm) * Dn + kb + fh * 16;
#pragma unroll
        for (int e = 0; e < 4; e++) {
            float4 v = *(const float4*)(src + 4 * e);
            int c = fh * 16 + 4 * e;
            As[fm][c + 0] = tf32rf(v.x); As[fm][c + 1] = tf32rf(v.y);
            As[fm][c + 2] = tf32rf(v.z); As[fm][c + 3] = tf32rf(v.w);
        }
        __syncthreads();
#pragma unroll
        for (int k0 = 0; k0 < 32; k0 += 8) {
            uint32_t b0[4], b1[4];
#pragma unroll
            for (int ni = 0; ni < 4; ni++) {
                int n = nloc0 + wn * 32 + ni * 8 + grp;
                b0[ni] = tf32r(W[(size_t)n * Dn + kb + k0 + q]);
                b1[ni] = tf32r(W[(size_t)n * Dn + kb + k0 + q + 4]);
            }
#pragma unroll
            for (int mi = 0; mi < 2; mi++) {
                int mb = wm * 32 + mi * 16;
                uint32_t a0 = __float_as_uint(As[mb + grp][k0 + q]);
                uint32_t a1 = __float_as_uint(As[mb + 8 + grp][k0 + q]);
                uint32_t a2 = __float_as_uint(As[mb + grp][k0 + q + 4]);
                uint32_t a3 = __float_as_uint(As[mb + 8 + grp][k0 + q + 4]);
#pragma unroll
                for (int ni = 0; ni < 4; ni++)
                    mma8(acc[mi][ni], a0, a1, a2, a3, b0[ni], b1[ni]);
            }
        }
        __syncthreads();
    }
    float* dst = g_part[blockIdx.z];
#pragma unroll
    for (int mi = 0; mi < 2; mi++) {
        int r0 = m0 + wm * 32 + mi * 16 + grp;
#pragma unroll
        for (int ni = 0; ni < 4; ni++) {
            int c = n0 + wn * 32 + ni * 8 + 2 * q;
            dst[(size_t)r0 * 512 + c]           = acc[mi][ni][0];
            dst[(size_t)r0 * 512 + c + 1]       = acc[mi][ni][1];
            dst[(size_t)(r0 + 8) * 512 + c]     = acc[mi][ni][2];
            dst[(size_t)(r0 + 8) * 512 + c + 1] = acc[mi][ni][3];
        }
    }
}

__global__ void combine_proj_kernel(const float* __restrict__ left_b,
                                    const float* __restrict__ right_b) {
    int i = blockIdx.x * blockDim.x + threadIdx.x;   // 512*512
    if (i < 512 * 512) {
        int m = i >> 9, n = i & 511;
        float s = g_part[0][i] + g_part[1][i] + g_part[2][i];
        if (n < Hn) g_left [(size_t)m * Hn + n]      = s + left_b[n];
        else        g_right[(size_t)m * Hn + n - Hn] = s + right_b[n - Hn];
    }
}

// ---------------- fused pair-scorer + probs (R8 config, measured best) -----
// write_scores=0: write probs only (iterations).  =1: write scores only (final).
// block = 256 threads = 8 warps (4 m x 2 n), block tile 128j x 64l, K=h(256)
// grid: (2, i=256, b=2)
__global__ __launch_bounds__(256) void scores_kernel(
        const int* __restrict__ span_begin, const int* __restrict__ span_end,
        const float* __restrict__ dist_emb, const float* __restrict__ out_b,
        const float* __restrict__ mask, float* __restrict__ scores,
        int write_scores) {
    __shared__ float As[128][36];
    __shared__ float oS[32][72];
    __shared__ float leftS[Hn];
    const int tid = threadIdx.x;
    const int warp = tid >> 5, lane = tid & 31;
    const int wm = warp & 3, wn = warp >> 2;
    const int grp = lane >> 2, q = lane & 3;
    const int b = blockIdx.z, i = blockIdx.y, j0 = blockIdx.x * 128;
    const int fm = tid >> 1, fh = tid & 1;
    const int fn = tid & 63, fk = tid >> 6;

    leftS[tid] = g_left[(size_t)(b * Kn + i) * Hn + tid];
    int dd = span_begin[b * Kn + j0 + fm] - span_end[b * Kn + i];
    int ad = abs(dd); const int bkt = ad > 63 ? 63 : ad;
    __syncthreads();

    float acc[2][4][4] = {};
    for (int hb = 0; hb < Hn; hb += 32) {
        const float* rsrc = g_right + (size_t)(b * Kn + j0 + fm) * Hn + hb + fh * 16;
        const float* dsrc = dist_emb + (size_t)bkt * Hn + hb + fh * 16;
#pragma unroll
        for (int e = 0; e < 4; e++) {
            float4 rv = *(const float4*)(rsrc + 4 * e);
            float4 dv = *(const float4*)(dsrc + 4 * e);
            int c = fh * 16 + 4 * e;
            float4 lv = *(const float4*)(&leftS[hb + c]);
            As[fm][c + 0] = tf32rf(fmaxf(lv.x + rv.x + dv.x, 0.f));
            As[fm][c + 1] = tf32rf(fmaxf(lv.y + rv.y + dv.y, 0.f));
            As[fm][c + 2] = tf32rf(fmaxf(lv.z + rv.z + dv.z, 0.f));
            As[fm][c + 3] = tf32rf(fmaxf(lv.w + rv.w + dv.w, 0.f));
        }
#pragma unroll
        for (int e = 0; e < 8; e++)
            oS[fk * 8 + e][fn] = g_outwT[(size_t)(hb + fk * 8 + e) * Ln + fn];
        __syncthreads();
#pragma unroll
        for (int k0 = 0; k0 < 32; k0 += 8) {
            uint32_t b0[4], b1[4];
#pragma unroll
            for (int ni = 0; ni < 4; ni++) {
                int n = wn * 32 + ni * 8 + grp;
                b0[ni] = __float_as_uint(oS[k0 + q][n]);
                b1[ni] = __float_as_uint(oS[k0 + q + 4][n]);
            }
#pragma unroll
            for (int mi = 0; mi < 2; mi++) {
                int mb = wm * 32 + mi * 16;
                uint32_t a0 = __float_as_uint(As[mb + grp][k0 + q]);
                uint32_t a1 = __float_as_uint(As[mb + 8 + grp][k0 + q]);
                uint32_t a2 = __float_as_uint(As[mb + grp][k0 + q + 4]);
                uint32_t a3 = __float_as_uint(As[mb + 8 + grp][k0 + q + 4]);
#pragma unroll
                for (int ni = 0; ni < 4; ni++)
                    mma8(acc[mi][ni], a0, a1, a2, a3, b0[ni], b1[ni]);
            }
        }
        __syncthreads();
    }
    float* scRow = scores + (size_t)(b * Kn + i) * (Kn * Ln);
    float* prRow = g_probs + (size_t)(b * Kn + i) * (Kn * Ln);
    const float* mkRow = mask + (size_t)(b * Kn + i) * Kn;
#pragma unroll
    for (int mi = 0; mi < 2; mi++) {
        int j0l = wm * 32 + mi * 16 + grp;
        float mk0 = mkRow[j0 + j0l], mk1 = mkRow[j0 + j0l + 8];
#pragma unroll
        for (int ni = 0; ni < 4; ni++) {
            int c = wn * 32 + ni * 8 + 2 * q;
#pragma unroll
            for (int e = 0; e < 2; e++) {
                float s0 = acc[mi][ni][e]     + out_b[c + e];
                float s1 = acc[mi][ni][2 + e] + out_b[c + e];
                if (write_scores) {
                    scRow[(size_t)(j0 + j0l) * Ln + c + e]     = s0;
                    scRow[(size_t)(j0 + j0l + 8) * Ln + c + e] = s1;
                } else {
                    prRow[(size_t)(j0 + j0l) * Ln + c + e]     = tf32rf(sigmoidf(s0) * mk0);
                    prRow[(size_t)(j0 + j0l + 8) * Ln + c + e] = tf32rf(sigmoidf(s1) * mk1);
                }
            }
        }
    }
}

// ---------------- context GEMMs: both modes per block, split-M + split-K ---
// out[b,m,d] = sum_{i,l} probs[i,m,l]*u[i,d]*AwT[l,d]
//            + sum_{j,l} probs[m,j,l]*u[j,d]*BwT[l,d]
// block = 256 threads = 8 warps (4m x 2n), block tile 128m x 64d.
// grid (2 mt, 12 dt, z = b*6 + split(6, uneven 86,86,85,85,85,85)) = 288 = one wave
// Partials: g_part[split] (6 slots).
#define CTXT_SMEM ((2 * 128 * 36 + 2 * 64 * 72) * 4)
__global__ __launch_bounds__(256, 2) void ctxt_kernel(const float* __restrict__ u) {
    extern __shared__ float dsm[];
    float* AsBase = dsm;                  // 2 * 4608
    float* wS     = dsm + 2 * 4608;       // 2 * 4608 ([mode][64][72])
    const int tid = threadIdx.x;
    const int warp = tid >> 5, lane = tid & 31;
    const int wm = warp & 3, wn = warp >> 2;
    const int grp = lane >> 2, q = lane & 3;
    const int m0 = blockIdx.x * 128;
    const int d0 = blockIdx.y * 64;
    const int z = blockIdx.z;
    const int b = z / 6, split = z % 6;
    const float* probsB = g_probs + (size_t)b * Kn * Kn * Ln;
    const float* uB     = u       + (size_t)b * Kn * Dn;
    const int arow = tid >> 3, aq = tid & 7;

    int cn[4], dcol[4];
#pragma unroll
    for (int ni = 0; ni < 4; ni++) {
        cn[ni]   = wn * 32 + ni * 8 + grp;
        dcol[ni] = d0 + cn[ni];
    }

    // stage both weight slices once
    {
        int l = tid >> 2, c16 = (tid & 3) * 16;
#pragma unroll
        for (int e = 0; e < 4; e++) {
            int c = c16 + 4 * e;
            float4 va = *(const float4*)&g_AwT[(size_t)l * Dn + d0 + c];
            float4 vb = *(const float4*)&g_BwT[(size_t)l * Dn + d0 + c];
            wS[l * 72 + c + 0] = va.x; wS[l * 72 + c + 1] = va.y;
            wS[l * 72 + c + 2] = va.z; wS[l * 72 + c + 3] = va.w;
            wS[4608 + l * 72 + c + 0] = vb.x; wS[4608 + l * 72 + c + 1] = vb.y;
            wS[4608 + l * 72 + c + 2] = vb.z; wS[4608 + l * 72 + c + 3] = vb.w;
        }
    }

    // uneven split over 512 chunks of 32 r (per mode)
    const int begChunk = split * 85 + (split < 2 ? split : 2);
    const int NC       = 85 + (split < 2 ? 1 : 0);
    const int rBeg     = begChunk * 32;
    const int NCC      = 2 * NC;          // mode0 chunks then mode1 chunks

    auto issueA = [&](int cc, int buf) {
        int mode = (cc >= NC);
        int c = mode ? cc - NC : cc;
        int rb = rBeg + c * 32;
        int other = rb >> 6, l0 = rb & 63;
        float* dstBase = AsBase + buf * 4608;
#pragma unroll
        for (int p = 0; p < 4; p++) {
            int m = p * 32 + arow;
            const float* src = (mode == 0)
                ? &probsB[((size_t)other * Kn + m0 + m) * Ln + l0 + aq * 4]
                : &probsB[((size_t)(m0 + m) * Kn + other) * Ln + l0 + aq * 4];
            uint32_t daddr = (uint32_t)__cvta_generic_to_shared(dstBase + m * 36 + aq * 4);
            cp16(daddr, src);
        }
    };

    issueA(0, 0);
    asm volatile("cp.async.commit_group;\n");
    __syncthreads();   // wS visible

    float acc[2][4][4] = {};
    float uval[4], unext[4];
    {
        int o0 = rBeg >> 6;
#pragma unroll
        for (int ni = 0; ni < 4; ni++) uval[ni] = uB[(size_t)o0 * Dn + dcol[ni]];
    }

    for (int cc = 0; cc < NCC; cc++) {
        const int mode = (cc >= NC);
        const int c = mode ? cc - NC : cc;
        if (cc + 1 < NCC) {
            issueA(cc + 1, (cc + 1) & 1);
            int cm = (cc + 1 >= NC) ? cc + 1 - NC : cc + 1;
            int on = (rBeg + cm * 32) >> 6;
#pragma unroll
            for (int ni = 0; ni < 4; ni++) unext[ni] = uB[(size_t)on * Dn + dcol[ni]];
        }
        asm volatile("cp.async.commit_group;\n");
        if (cc + 1 < NCC) asm volatile("cp.async.wait_group 1;\n");
        else              asm volatile("cp.async.wait_group 0;\n");
        __syncthreads();

        const float* AsBuf = AsBase + (cc & 1) * 4608;
        const float* w = wS + mode * 4608;
        const int l0 = (rBeg + c * 32) & 63;
#pragma unroll
        for (int k0 = 0; k0 < 32; k0 += 8) {
            uint32_t b0[4], b1[4];
#pragma unroll
            for (int ni = 0; ni < 4; ni++) {
                float w0 = w[(l0 + k0 + q) * 72 + cn[ni]];
                float w1 = w[(l0 + k0 + q + 4) * 72 + cn[ni]];
                b0[ni] = __float_as_uint(uval[ni] * w0);   // mma reads tf32 bits (RZ)
                b1[ni] = __float_as_uint(uval[ni] * w1);
            }
#pragma unroll
            for (int mi = 0; mi < 2; mi++) {
                int mb = wm * 32 + mi * 16;
                uint32_t a0 = __float_as_uint(AsBuf[(mb + grp) * 36 + k0 + q]);
                uint32_t a1 = __float_as_uint(AsBuf[(mb + 8 + grp) * 36 + k0 + q]);
                uint32_t a2 = __float_as_uint(AsBuf[(mb + grp) * 36 + k0 + q + 4]);
                uint32_t a3 = __float_as_uint(AsBuf[(mb + 8 + grp) * 36 + k0 + q + 4]);
#pragma unroll
                for (int ni = 0; ni < 4; ni++)
                    mma8(acc[mi][ni], a0, a1, a2, a3, b0[ni], b1[ni]);
            }
        }
        __syncthreads();
#pragma unroll
        for (int ni = 0; ni < 4; ni++) uval[ni] = unext[ni];
    }

    float* dst = g_part[split];
#pragma unroll
    for (int mi = 0; mi < 2; mi++) {
        int row = m0 + wm * 32 + mi * 16 + grp;
#pragma unroll
        for (int ni = 0; ni < 4; ni++) {
            int c = d0 + wn * 32 + ni * 8 + 2 * q;
            *(float2*)&dst[((size_t)b * Kn + row) * Dn + c] =
                make_float2(acc[mi][ni][0], acc[mi][ni][1]);
            *(float2*)&dst[((size_t)b * Kn + row + 8) * Dn + c] =
                make_float2(acc[mi][ni][2], acc[mi][ni][3]);
        }
    }
}

__global__ void combine_kernel(const float* __restrict__ slen) {
    int i = blockIdx.x * blockDim.x + threadIdx.x;   // float4 index
    if (i < BKD / 4) {
        int b = (i * 4) / (Kn * Dn);
        float4 s = make_float4(0.f, 0.f, 0.f, 0.f);
#pragma unroll
        for (int p = 0; p < 6; p++) {
            float4 v = *(const float4*)&g_part[p][i * 4];
            s.x += v.x; s.y += v.y; s.z += v.z; s.w += v.w;
        }
        float inv = 1.0f / slen[b];
        s.x *= inv; s.y *= inv; s.z *= inv; s.w *= inv;
        *(float4*)&g_c[i * 4] = s;
    }
}

// ---------------- gate split-K: partials of [u|c] @ gate_w^T ---------------
// grid (4, 12, 4): split z covers k [z*384,(z+1)*384); partials -> slots 6..9
__global__ __launch_bounds__(256) void gate_kernel(const float* __restrict__ u,
        const float* __restrict__ gate_w) {
    __shared__ float As[128][36];
    const int tid = threadIdx.x;
    const int warp = tid >> 5, lane = tid & 31;
    const int wm = warp & 3, wn = warp >> 2;
    const int grp = lane >> 2, q = lane & 3;
    const int m0 = blockIdx.x * 128, n0 = blockIdx.y * 64;
    const int kBeg = blockIdx.z * 384, kEnd = kBeg + 384;
    const int fm = tid >> 1, fh = tid & 1;
    float acc[2][4][4] = {};

    for (int kb = kBeg; kb < kEnd; kb += 32) {
        const float* src = (kb < Dn)
            ? u   + (size_t)(m0 + fm) * Dn + kb + fh * 16
            : g_c + (size_t)(m0 + fm) * Dn + (kb - Dn) + fh * 16;
#pragma unroll
        for (int e = 0; e < 4; e++) {
            float4 v = *(const float4*)(src + 4 * e);
            int c = fh * 16 + 4 * e;
            As[fm][c + 0] = tf32rf(v.x); As[fm][c + 1] = tf32rf(v.y);
            As[fm][c + 2] = tf32rf(v.z); As[fm][c + 3] = tf32rf(v.w);
        }
        __syncthreads();
#pragma unroll
        for (int k0 = 0; k0 < 32; k0 += 8) {
            uint32_t b0[4], b1[4];
#pragma unroll
            for (int ni = 0; ni < 4; ni++) {
                int n = n0 + wn * 32 + ni * 8 + grp;
                b0[ni] = tf32r(gate_w[(size_t)n * (2 * Dn) + kb + k0 + q]);
                b1[ni] = tf32r(gate_w[(size_t)n * (2 * Dn) + kb + k0 + q + 4]);
            }
#pragma unroll
            for (int mi = 0; mi < 2; mi++) {
                int mb = wm * 32 + mi * 16;
                uint32_t a0 = __float_as_uint(As[mb + grp][k0 + q]);
                uint32_t a1 = __float_as_uint(As[mb + 8 + grp][k0 + q]);
                uint32_t a2 = __float_as_uint(As[mb + grp][k0 + q + 4]);
                uint32_t a3 = __float_as_uint(As[mb + 8 + grp][k0 + q + 4]);
#pragma unroll
                for (int ni = 0; ni < 4; ni++)
                    mma8(acc[mi][ni], a0, a1, a2, a3, b0[ni], b1[ni]);
            }
        }
        __syncthreads();
    }
    float* dst = g_part[6 + blockIdx.z];
#pragma unroll
    for (int mi = 0; mi < 2; mi++) {
        int r0 = m0 + wm * 32 + mi * 16 + grp;
#pragma unroll
        for (int ni = 0; ni < 4; ni++) {
            int c = n0 + wn * 32 + ni * 8 + 2 * q;
            dst[(size_t)r0 * Dn + c]           = acc[mi][ni][0];
            dst[(size_t)r0 * Dn + c + 1]       = acc[mi][ni][1];
            dst[(size_t)(r0 + 8) * Dn + c]     = acc[mi][ni][2];
            dst[(size_t)(r0 + 8) * Dn + c + 1] = acc[mi][ni][3];
        }
    }
}

__global__ void combine_gate_update_kernel(const float* __restrict__ gate_b,
                                           float* __restrict__ u) {
    int i = blockIdx.x * blockDim.x + threadIdx.x;   // float4 index
    if (i < BKD / 4) {
        int n = (i * 4) % Dn;
        float4 s3 = *(const float4*)&g_part[6][i * 4];
        float4 s4 = *(const float4*)&g_part[7][i * 4];
        float4 s5 = *(const float4*)&g_part[8][i * 4];
        float4 s6 = *(const float4*)&g_part[9][i * 4];
        float4 gb = *(const float4*)&gate_b[n];
        float4 uv = *(const float4*)&u[i * 4];
        float4 cv = *(const float4*)&g_c[i * 4];
        float g0 = sigmoidf(s3.x + s4.x + s5.x + s6.x + gb.x);
        float g1 = sigmoidf(s3.y + s4.y + s5.y + s6.y + gb.y);
        float g2 = sigmoidf(s3.z + s4.z + s5.z + s6.z + gb.z);
        float g3 = sigmoidf(s3.w + s4.w + s5.w + s6.w + gb.w);
        float4 o;
        o.x = g0 * uv.x + (1.0f - g0) * cv.x;
        o.y = g1 * uv.y + (1.0f - g1) * cv.y;
        o.z = g2 * uv.z + (1.0f - g2) * cv.z;
        o.w = g3 * uv.w + (1.0f - g3) * cv.w;
        *(float4*)&u[i * 4] = o;
    }
}

__global__ void scatter_kernel(const int* __restrict__ prune, const float* __restrict__ slen,
                               const float* __restrict__ u, float* __restrict__ outAll) {
    int i = blockIdx.x * blockDim.x + threadIdx.x;   // float4 index
    if (i < BKD / 4) {
        int idx = i * 4;
        int d = idx % Dn, bk = idx / Dn, b = bk / Kn, k = bk % Kn;
        if ((float)k < slen[b]) {
            int row = prune[bk];
            *(float4*)&outAll[((size_t)b * Nn + row) * Dn + d] = *(const float4*)&u[idx];
        }
    }
}

// ---------------- driver ---------------------------------------------------
extern "C" void kernel_launch(void* const* d_in, const int* in_sizes, int n_in,
                              void* d_out, int out_size) {
    (void)in_sizes; (void)n_in; (void)out_size;
    const float* all_vecs  = (const float*)d_in[0];
    const float* span_vecs = (const float*)d_in[1];
    const int*   span_beg  = (const int*)  d_in[2];
    const int*   span_end  = (const int*)  d_in[3];
    const float* mask      = (const float*)d_in[4];
    const float* slen      = (const float*)d_in[5];
    const int*   prune     = (const int*)  d_in[6];
    const float* left_w    = (const float*)d_in[7];
    const float* left_b    = (const float*)d_in[8];
    const float* right_w   = (const float*)d_in[9];
    const float* right_b   = (const float*)d_in[10];
    const float* dist_emb  = (const float*)d_in[11];
    const float* out_w     = (const float*)d_in[12];
    const float* out_b     = (const float*)d_in[13];
    const float* A_w       = (const float*)d_in[14];
    const float* B_w       = (const float*)d_in[15];
    const float* gate_w    = (const float*)d_in[16];
    const float* gate_b    = (const float*)d_in[17];

    float* outAll = (float*)d_out;           // [B,N,D]
    float* outU   = outAll + BND;            // [B,K,D]
    float* outS   = outU + BKD;              // [B,K,K,L]

    static int attr_done = 0;
    if (!attr_done) {
        cudaFuncSetAttribute(ctxt_kernel,
                             cudaFuncAttributeMaxDynamicSharedMemorySize, CTXT_SMEM);
        attr_done = 1;
    }

    prep_kernel<<<(Ln * Dn + 255) / 256, 256>>>(out_w, A_w, B_w);
    copy_init_kernel<<<(BND / 16 + 255) / 256, 256>>>(all_vecs, span_vecs, outAll, outU);

    proj_kernel<<<dim3(4, 8, 3), 256>>>(outU, left_w, right_w);
    combine_proj_kernel<<<(512 * 512 + 255) / 256, 256>>>(left_b, right_b);
    scores_kernel<<<dim3(2, Kn, Bn), 256>>>(span_beg, span_end, dist_emb, out_b, mask, outS, 0);

    for (int t = 0; t < 3; t++) {
        ctxt_kernel<<<dim3(2, 12, 12), 256, CTXT_SMEM>>>(outU);
        combine_kernel<<<(BKD / 4 + 255) / 256, 256>>>(slen);
        gate_kernel<<<dim3(4, 12, 4), 256>>>(outU, gate_w);
        combine_gate_update_kernel<<<(BKD / 4 + 255) / 256, 256>>>(gate_b, outU);
        proj_kernel<<<dim3(4, 8, 3), 256>>>(outU, left_w, right_w);
        combine_proj_kernel<<<(512 * 512 + 255) / 256, 256>>>(left_b, right_b);
        scores_kernel<<<dim3(2, Kn, Bn), 256>>>(span_beg, span_end, dist_emb, out_b, mask,
                                                outS, t == 2 ? 1 : 0);
    }

    scatter_kernel<<<(BKD / 4 + 255) / 256, 256>>>(prune, slen, outU, outAll);
}

// round 14
// speedup vs baseline: 1.0782x; 1.0782x over previous
#include <cuda_runtime.h>
#include <cstdint>

#define Bn 2
#define Nn 2048
#define Kn 256
#define Dn 768
#define Hn 256
#define Ln 64
#define BND (Bn*Nn*Dn)
#define BKD (Bn*Kn*Dn)
#define BKH (Bn*Kn*Hn)
#define BKKL ((size_t)Bn*Kn*Kn*Ln)

// ---------------- scratch (device globals; no allocations allowed) ----------
__device__ float g_left [BKH];
__device__ float g_right[BKH];
__device__ float g_outwT[Hn*Ln];      // [h][l], tf32-rounded
__device__ float g_AwT  [Ln*Dn];      // [l][d], tf32-rounded
__device__ float g_BwT  [Ln*Dn];      // [l][d], tf32-rounded
__device__ float g_probs[BKKL];       // sigmoid(score)*mask, tf32-rounded
__device__ float g_part [16][BKD];    // ctxt partials (0..11); proj reuses 0..2, gate 3..6
__device__ float g_c    [BKD];

__device__ __forceinline__ float sigmoidf(float x) {
    return 1.0f / (1.0f + __expf(-x));
}
__device__ __forceinline__ uint32_t tf32r(float x) {
    uint32_t u; asm("cvt.rna.tf32.f32 %0, %1;" : "=r"(u) : "f"(x)); return u;
}
__device__ __forceinline__ float tf32rf(float x) {
    return __uint_as_float(tf32r(x));
}
__device__ __forceinline__ void mma8(float c[4], uint32_t a0, uint32_t a1, uint32_t a2,
                                     uint32_t a3, uint32_t b0, uint32_t b1) {
    asm("mma.sync.aligned.m16n8k8.row.col.f32.tf32.tf32.f32 "
        "{%0,%1,%2,%3},{%4,%5,%6,%7},{%8,%9},{%0,%1,%2,%3};"
        : "+f"(c[0]), "+f"(c[1]), "+f"(c[2]), "+f"(c[3])
        : "r"(a0), "r"(a1), "r"(a2), "r"(a3), "r"(b0), "r"(b1));
}
__device__ __forceinline__ void cp16(uint32_t daddr, const void* src) {
    asm volatile("cp.async.cg.shared.global [%0], [%1], 16;\n" :: "r"(daddr), "l"(src));
}

// ---------------- prep: tf32-rounded weight transposes ---------------------
__global__ void prep_kernel(const float* __restrict__ out_w,
                            const float* __restrict__ A_w,
                            const float* __restrict__ B_w) {
    int i = blockIdx.x * blockDim.x + threadIdx.x;
    if (i < Hn * Ln) { int h = i / Ln, l = i - h * Ln; g_outwT[i] = tf32rf(out_w[l * Hn + h]); }
    if (i < Ln * Dn) { int l = i / Dn, d = i - l * Dn; g_AwT[i] = tf32rf(A_w[d * Ln + l]);
                                                      g_BwT[i] = tf32rf(B_w[d * Ln + l]); }
}

// 4 float4 per thread (MLP=4)
__global__ void copy_init_kernel(const float* __restrict__ all_vecs,
                                 const float* __restrict__ span_vecs,
                                 float* __restrict__ outAll,
                                 float* __restrict__ outU) {
    const int stride = BND / 16;
    int i = blockIdx.x * blockDim.x + threadIdx.x;
    if (i < stride) {
#pragma unroll
        for (int e = 0; e < 4; e++) {
            int idx = i + e * stride;
            ((float4*)outAll)[idx] = ((const float4*)all_vecs)[idx];
        }
        if (i < BKD / 4) ((float4*)outU)[i] = ((const float4*)span_vecs)[i];
    }
}

// ---------------- proj split-K: partials for u @ [left_w|right_w]^T --------
// grid (4, 8, 3): m-tile 128, n-tile 64 over 512 cols, split z covers k [z*256,(z+1)*256)
__global__ __launch_bounds__(256) void proj_kernel(const float* __restrict__ u,
        const float* __restrict__ left_w, const float* __restrict__ right_w) {
    __shared__ float As[128][36];
    const int tid = threadIdx.x;
    const int warp = tid >> 5, lane = tid & 31;
    const int wm = warp & 3, wn = warp >> 2;
    const int grp = lane >> 2, q = lane & 3;
    const int m0 = blockIdx.x * 128, n0 = blockIdx.y * 64;
    const int kBeg = blockIdx.z * 256, kEnd = kBeg + 256;
    const bool isL = (n0 < Hn);
    const float* W = isL ? left_w : right_w;
    const int nloc0 = isL ? n0 : n0 - Hn;
    const int fm = tid >> 1, fh = tid & 1;
    float acc[2][4][4] = {};

    for (int kb = kBeg; kb < kEnd; kb += 32) {
        const float* src = u + (size_t)(m0 + fm) * Dn + kb + fh * 16;
#pragma unroll
        for (int e = 0; e < 4; e++) {
            float4 v = *(const float4*)(src + 4 * e);
            int c = fh * 16 + 4 * e;
            As[fm][c + 0] = tf32rf(v.x); As[fm][c + 1] = tf32rf(v.y);
            As[fm][c + 2] = tf32rf(v.z); As[fm][c + 3] = tf32rf(v.w);
        }
        __syncthreads();
#pragma unroll
        for (int k0 = 0; k0 < 32; k0 += 8) {
            uint32_t b0[4], b1[4];
#pragma unroll
            for (int ni = 0; ni < 4; ni++) {
                int n = nloc0 + wn * 32 + ni * 8 + grp;
                b0[ni] = tf32r(W[(size_t)n * Dn + kb + k0 + q]);
                b1[ni] = tf32r(W[(size_t)n * Dn + kb + k0 + q + 4]);
            }
#pragma unroll
            for (int mi = 0; mi < 2; mi++) {
                int mb = wm * 32 + mi * 16;
                uint32_t a0 = __float_as_uint(As[mb + grp][k0 + q]);
                uint32_t a1 = __float_as_uint(As[mb + 8 + grp][k0 + q]);
                uint32_t a2 = __float_as_uint(As[mb + grp][k0 + q + 4]);
                uint32_t a3 = __float_as_uint(As[mb + 8 + grp][k0 + q + 4]);
#pragma unroll
                for (int ni = 0; ni < 4; ni++)
                    mma8(acc[mi][ni], a0, a1, a2, a3, b0[ni], b1[ni]);
            }
        }
        __syncthreads();
    }
    float* dst = g_part[blockIdx.z];
#pragma unroll
    for (int mi = 0; mi < 2; mi++) {
        int r0 = m0 + wm * 32 + mi * 16 + grp;
#pragma unroll
        for (int ni = 0; ni < 4; ni++) {
            int c = n0 + wn * 32 + ni * 8 + 2 * q;
            dst[(size_t)r0 * 512 + c]           = acc[mi][ni][0];
            dst[(size_t)r0 * 512 + c + 1]       = acc[mi][ni][1];
            dst[(size_t)(r0 + 8) * 512 + c]     = acc[mi][ni][2];
            dst[(size_t)(r0 + 8) * 512 + c + 1] = acc[mi][ni][3];
        }
    }
}

__global__ void combine_proj_kernel(const float* __restrict__ left_b,
                                    const float* __restrict__ right_b) {
    int i = blockIdx.x * blockDim.x + threadIdx.x;   // 512*512
    if (i < 512 * 512) {
        int m = i >> 9, n = i & 511;
        float s = g_part[0][i] + g_part[1][i] + g_part[2][i];
        if (n < Hn) g_left [(size_t)m * Hn + n]      = s + left_b[n];
        else        g_right[(size_t)m * Hn + n - Hn] = s + right_b[n - Hn];
    }
}

// ---------------- fused pair-scorer + probs (R8 config, measured best) -----
// write_scores=0: probs only.  =1: scores only (final call).
// block = 256 threads = 8 warps (4 m x 2 n), block tile 128j x 64l, K=h(256)
// grid: (2, i=256, b=2)
__global__ __launch_bounds__(256) void scores_kernel(
        const int* __restrict__ span_begin, const int* __restrict__ span_end,
        const float* __restrict__ dist_emb, const float* __restrict__ out_b,
        const float* __restrict__ mask, float* __restrict__ scores,
        int write_scores) {
    __shared__ float As[128][36];
    __shared__ float oS[32][72];
    __shared__ float leftS[Hn];
    const int tid = threadIdx.x;
    const int warp = tid >> 5, lane = tid & 31;
    const int wm = warp & 3, wn = warp >> 2;
    const int grp = lane >> 2, q = lane & 3;
    const int b = blockIdx.z, i = blockIdx.y, j0 = blockIdx.x * 128;
    const int fm = tid >> 1, fh = tid & 1;
    const int fn = tid & 63, fk = tid >> 6;

    leftS[tid] = g_left[(size_t)(b * Kn + i) * Hn + tid];
    int dd = span_begin[b * Kn + j0 + fm] - span_end[b * Kn + i];
    int ad = abs(dd); const int bkt = ad > 63 ? 63 : ad;
    __syncthreads();

    float acc[2][4][4] = {};
    for (int hb = 0; hb < Hn; hb += 32) {
        const float* rsrc = g_right + (size_t)(b * Kn + j0 + fm) * Hn + hb + fh * 16;
        const float* dsrc = dist_emb + (size_t)bkt * Hn + hb + fh * 16;
#pragma unroll
        for (int e = 0; e < 4; e++) {
            float4 rv = *(const float4*)(rsrc + 4 * e);
            float4 dv = *(const float4*)(dsrc + 4 * e);
            int c = fh * 16 + 4 * e;
            float4 lv = *(const float4*)(&leftS[hb + c]);
            As[fm][c + 0] = tf32rf(fmaxf(lv.x + rv.x + dv.x, 0.f));
            As[fm][c + 1] = tf32rf(fmaxf(lv.y + rv.y + dv.y, 0.f));
            As[fm][c + 2] = tf32rf(fmaxf(lv.z + rv.z + dv.z, 0.f));
            As[fm][c + 3] = tf32rf(fmaxf(lv.w + rv.w + dv.w, 0.f));
        }
#pragma unroll
        for (int e = 0; e < 8; e++)
            oS[fk * 8 + e][fn] = g_outwT[(size_t)(hb + fk * 8 + e) * Ln + fn];
        __syncthreads();
#pragma unroll
        for (int k0 = 0; k0 < 32; k0 += 8) {
            uint32_t b0[4], b1[4];
#pragma unroll
            for (int ni = 0; ni < 4; ni++) {
                int n = wn * 32 + ni * 8 + grp;
                b0[ni] = __float_as_uint(oS[k0 + q][n]);
                b1[ni] = __float_as_uint(oS[k0 + q + 4][n]);
            }
#pragma unroll
            for (int mi = 0; mi < 2; mi++) {
                int mb = wm * 32 + mi * 16;
                uint32_t a0 = __float_as_uint(As[mb + grp][k0 + q]);
                uint32_t a1 = __float_as_uint(As[mb + 8 + grp][k0 + q]);
                uint32_t a2 = __float_as_uint(As[mb + grp][k0 + q + 4]);
                uint32_t a3 = __float_as_uint(As[mb + 8 + grp][k0 + q + 4]);
#pragma unroll
                for (int ni = 0; ni < 4; ni++)
                    mma8(acc[mi][ni], a0, a1, a2, a3, b0[ni], b1[ni]);
            }
        }
        __syncthreads();
    }
    float* scRow = scores + (size_t)(b * Kn + i) * (Kn * Ln);
    float* prRow = g_probs + (size_t)(b * Kn + i) * (Kn * Ln);
    const float* mkRow = mask + (size_t)(b * Kn + i) * Kn;
#pragma unroll
    for (int mi = 0; mi < 2; mi++) {
        int j0l = wm * 32 + mi * 16 + grp;
        float mk0 = mkRow[j0 + j0l], mk1 = mkRow[j0 + j0l + 8];
#pragma unroll
        for (int ni = 0; ni < 4; ni++) {
            int c = wn * 32 + ni * 8 + 2 * q;
#pragma unroll
            for (int e = 0; e < 2; e++) {
                float s0 = acc[mi][ni][e]     + out_b[c + e];
                float s1 = acc[mi][ni][2 + e] + out_b[c + e];
                if (write_scores) {
                    scRow[(size_t)(j0 + j0l) * Ln + c + e]     = s0;
                    scRow[(size_t)(j0 + j0l + 8) * Ln + c + e] = s1;
                } else {
                    prRow[(size_t)(j0 + j0l) * Ln + c + e]     = tf32rf(sigmoidf(s0) * mk0);
                    prRow[(size_t)(j0 + j0l + 8) * Ln + c + e] = tf32rf(sigmoidf(s1) * mk1);
                }
            }
        }
    }
}

// ---------------- context GEMMs: cp.async double-buffered, single-wave -----
// block = 256 threads = 8 warps (4m x 2n), block tile 256m x 64d.
// 6 UNEVEN k-splits (86,86,85,85,85,85 chunks of 512) -> grid 288 = one wave
// grid: (1, d-tile=12, z = b*12 + mode*6 + split)
#define CTXT_SMEM ((2 * 256 * 36 + 64 * 72) * 4)
__global__ __launch_bounds__(256, 2) void ctxt_kernel(const float* __restrict__ u) {
    extern __shared__ float dsm[];
    float* AsBase = dsm;
    float* wS     = dsm + 2 * 256 * 36;
    const int tid = threadIdx.x;
    const int warp = tid >> 5, lane = tid & 31;
    const int wm = warp & 3, wn = warp >> 2;
    const int grp = lane >> 2, q = lane & 3;
    const int z = blockIdx.z;
    const int b = z / 12, r12 = z % 12, mode = r12 / 6, split = r12 % 6;
    const int d0 = blockIdx.y * 64;
    const float* wT = (mode == 0) ? g_AwT : g_BwT;
    const float* probsB = g_probs + (size_t)b * Kn * Kn * Ln;
    const float* uB     = u       + (size_t)b * Kn * Dn;
    const int arow = tid >> 3, aq = tid & 7;

    int cn[4], dcol[4];
#pragma unroll
    for (int ni = 0; ni < 4; ni++) {
        cn[ni]   = wn * 32 + ni * 8 + grp;
        dcol[ni] = d0 + cn[ni];
    }

    {
        int l = tid >> 2, c16 = (tid & 3) * 16;
#pragma unroll
        for (int e = 0; e < 4; e++) {
            float4 v = *(const float4*)&wT[(size_t)l * Dn + d0 + c16 + 4 * e];
            int c = c16 + 4 * e;
            wS[l * 72 + c + 0] = v.x; wS[l * 72 + c + 1] = v.y;
            wS[l * 72 + c + 2] = v.z; wS[l * 72 + c + 3] = v.w;
        }
    }

    // uneven split over 512 chunks of 32 r
    const int begChunk = split * 85 + (split < 2 ? split : 2);
    const int NC       = 85 + (split < 2 ? 1 : 0);
    const int rBeg     = begChunk * 32;

    auto issueA = [&](int c, int buf) {
        int rb = rBeg + c * 32;
        int other = rb >> 6, l0 = rb & 63;
        float* dstBase = AsBase + buf * 9216;
#pragma unroll
        for (int p = 0; p < 8; p++) {
            int m = p * 32 + arow;
            const float* src = (mode == 0)
                ? &probsB[((size_t)other * Kn + m) * Ln + l0 + aq * 4]
                : &probsB[((size_t)m * Kn + other) * Ln + l0 + aq * 4];
            uint32_t daddr = (uint32_t)__cvta_generic_to_shared(dstBase + m * 36 + aq * 4);
            cp16(daddr, src);
        }
    };

    issueA(0, 0);
    asm volatile("cp.async.commit_group;\n");
    __syncthreads();

    float acc[4][4][4] = {};
    float uval[4], unext[4];
    {
        int o0 = rBeg >> 6;
#pragma unroll
        for (int ni = 0; ni < 4; ni++) uval[ni] = uB[(size_t)o0 * Dn + dcol[ni]];
    }

    for (int c = 0; c < NC; c++) {
        if (c + 1 < NC) {
            issueA(c + 1, (c + 1) & 1);
            int on = (rBeg + (c + 1) * 32) >> 6;
#pragma unroll
            for (int ni = 0; ni < 4; ni++) unext[ni] = uB[(size_t)on * Dn + dcol[ni]];
        }
        asm volatile("cp.async.commit_group;\n");
        if (c + 1 < NC) asm volatile("cp.async.wait_group 1;\n");
        else            asm volatile("cp.async.wait_group 0;\n");
        __syncthreads();

        const float* AsBuf = AsBase + (c & 1) * 9216;
        const int l0 = (rBeg + c * 32) & 63;
#pragma unroll
        for (int k0 = 0; k0 < 32; k0 += 8) {
            uint32_t b0[4], b1[4];
#pragma unroll
            for (int ni = 0; ni < 4; ni++) {
                float w0 = wS[(l0 + k0 + q) * 72 + cn[ni]];
                float w1 = wS[(l0 + k0 + q + 4) * 72 + cn[ni]];
                b0[ni] = __float_as_uint(uval[ni] * w0);   // mma reads tf32 bits (RZ)
                b1[ni] = __float_as_uint(uval[ni] * w1);
            }
#pragma unroll
            for (int mi = 0; mi < 4; mi++) {
                int mb = wm * 64 + mi * 16;
                uint32_t a0 = __float_as_uint(AsBuf[(mb + grp) * 36 + k0 + q]);
                uint32_t a1 = __float_as_uint(AsBuf[(mb + 8 + grp) * 36 + k0 + q]);
                uint32_t a2 = __float_as_uint(AsBuf[(mb + grp) * 36 + k0 + q + 4]);
                uint32_t a3 = __float_as_uint(AsBuf[(mb + 8 + grp) * 36 + k0 + q + 4]);
#pragma unroll
                for (int ni = 0; ni < 4; ni++)
                    mma8(acc[mi][ni], a0, a1, a2, a3, b0[ni], b1[ni]);
            }
        }
        __syncthreads();
#pragma unroll
        for (int ni = 0; ni < 4; ni++) uval[ni] = unext[ni];
    }

    float* dst = g_part[mode * 6 + split];
#pragma unroll
    for (int mi = 0; mi < 4; mi++) {
        int row = wm * 64 + mi * 16 + grp;
#pragma unroll
        for (int ni = 0; ni < 4; ni++) {
            int c = d0 + wn * 32 + ni * 8 + 2 * q;
            *(float2*)&dst[((size_t)b * Kn + row) * Dn + c] =
                make_float2(acc[mi][ni][0], acc[mi][ni][1]);
            *(float2*)&dst[((size_t)b * Kn + row + 8) * Dn + c] =
                make_float2(acc[mi][ni][2], acc[mi][ni][3]);
        }
    }
}

__global__ void combine_kernel(const float* __restrict__ slen) {
    int i = blockIdx.x * blockDim.x + threadIdx.x;   // float4 index
    if (i < BKD / 4) {
        int b = (i * 4) / (Kn * Dn);
        float4 s = make_float4(0.f, 0.f, 0.f, 0.f);
#pragma unroll
        for (int p = 0; p < 12; p++) {
            float4 v = *(const float4*)&g_part[p][i * 4];
            s.x += v.x; s.y += v.y; s.z += v.z; s.w += v.w;
        }
        float inv = 1.0f / slen[b];
        s.x *= inv; s.y *= inv; s.z *= inv; s.w *= inv;
        *(float4*)&g_c[i * 4] = s;
    }
}

// ---------------- gate split-K: partials of [u|c] @ gate_w^T ---------------
// grid (4, 12, 4): split z covers k [z*384,(z+1)*384); partials -> slots 12..15
__global__ __launch_bounds__(256) void gate_kernel(const float* __restrict__ u,
        const float* __restrict__ gate_w) {
    __shared__ float As[128][36];
    const int tid = threadIdx.x;
    const int warp = tid >> 5, lane = tid & 31;
    const int wm = warp & 3, wn = warp >> 2;
    const int grp = lane >> 2, q = lane & 3;
    const int m0 = blockIdx.x * 128, n0 = blockIdx.y * 64;
    const int kBeg = blockIdx.z * 384, kEnd = kBeg + 384;
    const int fm = tid >> 1, fh = tid & 1;
    float acc[2][4][4] = {};

    for (int kb = kBeg; kb < kEnd; kb += 32) {
        const float* src = (kb < Dn)
            ? u   + (size_t)(m0 + fm) * Dn + kb + fh * 16
            : g_c + (size_t)(m0 + fm) * Dn + (kb - Dn) + fh * 16;
#pragma unroll
        for (int e = 0; e < 4; e++) {
            float4 v = *(const float4*)(src + 4 * e);
            int c = fh * 16 + 4 * e;
            As[fm][c + 0] = tf32rf(v.x); As[fm][c + 1] = tf32rf(v.y);
            As[fm][c + 2] = tf32rf(v.z); As[fm][c + 3] = tf32rf(v.w);
        }
        __syncthreads();
#pragma unroll
        for (int k0 = 0; k0 < 32; k0 += 8) {
            uint32_t b0[4], b1[4];
#pragma unroll
            for (int ni = 0; ni < 4; ni++) {
                int n = n0 + wn * 32 + ni * 8 + grp;
                b0[ni] = tf32r(gate_w[(size_t)n * (2 * Dn) + kb + k0 + q]);
                b1[ni] = tf32r(gate_w[(size_t)n * (2 * Dn) + kb + k0 + q + 4]);
            }
#pragma unroll
            for (int mi = 0; mi < 2; mi++) {
                int mb = wm * 32 + mi * 16;
                uint32_t a0 = __float_as_uint(As[mb + grp][k0 + q]);
                uint32_t a1 = __float_as_uint(As[mb + 8 + grp][k0 + q]);
                uint32_t a2 = __float_as_uint(As[mb + grp][k0 + q + 4]);
                uint32_t a3 = __float_as_uint(As[mb + 8 + grp][k0 + q + 4]);
#pragma unroll
                for (int ni = 0; ni < 4; ni++)
                    mma8(acc[mi][ni], a0, a1, a2, a3, b0[ni], b1[ni]);
            }
        }
        __syncthreads();
    }
    float* dst = g_part[12 + blockIdx.z];
#pragma unroll
    for (int mi = 0; mi < 2; mi++) {
        int r0 = m0 + wm * 32 + mi * 16 + grp;
#pragma unroll
        for (int ni = 0; ni < 4; ni++) {
            int c = n0 + wn * 32 + ni * 8 + 2 * q;
            dst[(size_t)r0 * Dn + c]           = acc[mi][ni][0];
            dst[(size_t)r0 * Dn + c + 1]       = acc[mi][ni][1];
            dst[(size_t)(r0 + 8) * Dn + c]     = acc[mi][ni][2];
            dst[(size_t)(r0 + 8) * Dn + c + 1] = acc[mi][ni][3];
        }
    }
}

__global__ void combine_gate_update_kernel(const float* __restrict__ gate_b,
                                           float* __restrict__ u) {
    int i = blockIdx.x * blockDim.x + threadIdx.x;   // float4 index
    if (i < BKD / 4) {
        int n = (i * 4) % Dn;
        float4 s3 = *(const float4*)&g_part[12][i * 4];
        float4 s4 = *(const float4*)&g_part[13][i * 4];
        float4 s5 = *(const float4*)&g_part[14][i * 4];
        float4 s6 = *(const float4*)&g_part[15][i * 4];
        float4 gb = *(const float4*)&gate_b[n];
        float4 uv = *(const float4*)&u[i * 4];
        float4 cv = *(const float4*)&g_c[i * 4];
        float g0 = sigmoidf(s3.x + s4.x + s5.x + s6.x + gb.x);
        float g1 = sigmoidf(s3.y + s4.y + s5.y + s6.y + gb.y);
        float g2 = sigmoidf(s3.z + s4.z + s5.z + s6.z + gb.z);
        float g3 = sigmoidf(s3.w + s4.w + s5.w + s6.w + gb.w);
        float4 o;
        o.x = g0 * uv.x + (1.0f - g0) * cv.x;
        o.y = g1 * uv.y + (1.0f - g1) * cv.y;
        o.z = g2 * uv.z + (1.0f - g2) * cv.z;
        o.w = g3 * uv.w + (1.0f - g3) * cv.w;
        *(float4*)&u[i * 4] = o;
    }
}

__global__ void scatter_kernel(const int* __restrict__ prune, const float* __restrict__ slen,
                               const float* __restrict__ u, float* __restrict__ outAll) {
    int i = blockIdx.x * blockDim.x + threadIdx.x;   // float4 index
    if (i < BKD / 4) {
        int idx = i * 4;
        int d = idx % Dn, bk = idx / Dn, b = bk / Kn, k = bk % Kn;
        if ((float)k < slen[b]) {
            int row = prune[bk];
            *(float4*)&outAll[((size_t)b * Nn + row) * Dn + d] = *(const float4*)&u[idx];
        }
    }
}

// ---------------- driver ---------------------------------------------------
extern "C" void kernel_launch(void* const* d_in, const int* in_sizes, int n_in,
                              void* d_out, int out_size) {
    (void)in_sizes; (void)n_in; (void)out_size;
    const float* all_vecs  = (const float*)d_in[0];
    const float* span_vecs = (const float*)d_in[1];
    const int*   span_beg  = (const int*)  d_in[2];
    const int*   span_end  = (const int*)  d_in[3];
    const float* mask      = (const float*)d_in[4];
    const float* slen      = (const float*)d_in[5];
    const int*   prune     = (const int*)  d_in[6];
    const float* left_w    = (const float*)d_in[7];
    const float* left_b    = (const float*)d_in[8];
    const float* right_w   = (const float*)d_in[9];
    const float* right_b   = (const float*)d_in[10];
    const float* dist_emb  = (const float*)d_in[11];
    const float* out_w     = (const float*)d_in[12];
    const float* out_b     = (const float*)d_in[13];
    const float* A_w       = (const float*)d_in[14];
    const float* B_w       = (const float*)d_in[15];
    const float* gate_w    = (const float*)d_in[16];
    const float* gate_b    = (const float*)d_in[17];

    float* outAll = (float*)d_out;           // [B,N,D]
    float* outU   = outAll + BND;            // [B,K,D]
    float* outS   = outU + BKD;              // [B,K,K,L]

    static int attr_done = 0;
    if (!attr_done) {
        cudaFuncSetAttribute(ctxt_kernel,
                             cudaFuncAttributeMaxDynamicSharedMemorySize, CTXT_SMEM);
        attr_done = 1;
    }

    prep_kernel<<<(Ln * Dn + 255) / 256, 256>>>(out_w, A_w, B_w);
    copy_init_kernel<<<(BND / 16 + 255) / 256, 256>>>(all_vecs, span_vecs, outAll, outU);

    proj_kernel<<<dim3(4, 8, 3), 256>>>(outU, left_w, right_w);
    combine_proj_kernel<<<(512 * 512 + 255) / 256, 256>>>(left_b, right_b);
    scores_kernel<<<dim3(2, Kn, Bn), 256>>>(span_beg, span_end, dist_emb, out_b, mask, outS, 0);

    for (int t = 0; t < 3; t++) {
        ctxt_kernel<<<dim3(1, 12, 24), 256, CTXT_SMEM>>>(outU);
        combine_kernel<<<(BKD / 4 + 255) / 256, 256>>>(slen);
        gate_kernel<<<dim3(4, 12, 4), 256>>>(outU, gate_w);
        combine_gate_update_kernel<<<(BKD / 4 + 255) / 256, 256>>>(gate_b, outU);
        proj_kernel<<<dim3(4, 8, 3), 256>>>(outU, left_w, right_w);
        combine_proj_kernel<<<(512 * 512 + 255) / 256, 256>>>(left_b, right_b);
        scores_kernel<<<dim3(2, Kn, Bn), 256>>>(span_beg, span_end, dist_emb, out_b, mask,
                                                outS, t == 2 ? 1 : 0);
    }

    scatter_kernel<<<(BKD / 4 + 255) / 256, 256>>>(prune, slen, outU, outAll);
}

// round 15
// speedup vs baseline: 1.1615x; 1.0772x over previous
#include <cuda_runtime.h>
#include <cstdint>

#define Bn 2
#define Nn 2048
#define Kn 256
#define Dn 768
#define Hn 256
#define Ln 64
#define BND (Bn*Nn*Dn)
#define BKD (Bn*Kn*Dn)
#define BKH (Bn*Kn*Hn)
#define BKKL ((size_t)Bn*Kn*Kn*Ln)

// ---------------- scratch (device globals; no allocations allowed) ----------
__device__ float g_left [BKH];
__device__ float g_right[BKH];
__device__ float g_outwT[Hn*Ln];      // [h][l], tf32-rounded
__device__ float g_AwT  [Ln*Dn];      // [l][d], tf32-rounded
__device__ float g_BwT  [Ln*Dn];      // [l][d], tf32-rounded
__device__ float g_lrwT [Dn*512];     // [k][n] (n<256: left, else right), tf32-rounded
__device__ float g_gwT  [2*Dn*Dn];    // [k][n], tf32-rounded gate_w^T
__device__ float g_probs[BKKL];       // sigmoid(score)*mask, tf32-rounded
__device__ float g_part [16][BKD];    // ctxt partials (0..11); proj reuses 0..2, gate 12..15
__device__ float g_c    [BKD];

__device__ __forceinline__ float sigmoidf(float x) {
    return 1.0f / (1.0f + __expf(-x));
}
__device__ __forceinline__ uint32_t tf32r(float x) {
    uint32_t u; asm("cvt.rna.tf32.f32 %0, %1;" : "=r"(u) : "f"(x)); return u;
}
__device__ __forceinline__ float tf32rf(float x) {
    return __uint_as_float(tf32r(x));
}
__device__ __forceinline__ void mma8(float c[4], uint32_t a0, uint32_t a1, uint32_t a2,
                                     uint32_t a3, uint32_t b0, uint32_t b1) {
    asm("mma.sync.aligned.m16n8k8.row.col.f32.tf32.tf32.f32 "
        "{%0,%1,%2,%3},{%4,%5,%6,%7},{%8,%9},{%0,%1,%2,%3};"
        : "+f"(c[0]), "+f"(c[1]), "+f"(c[2]), "+f"(c[3])
        : "r"(a0), "r"(a1), "r"(a2), "r"(a3), "r"(b0), "r"(b1));
}
__device__ __forceinline__ void cp16(uint32_t daddr, const void* src) {
    asm volatile("cp.async.cg.shared.global [%0], [%1], 16;\n" :: "r"(daddr), "l"(src));
}

// ---------------- prep: tf32-rounded weight transposes ---------------------
__global__ void prep_kernel(const float* __restrict__ out_w,
                            const float* __restrict__ A_w,
                            const float* __restrict__ B_w,
                            const float* __restrict__ left_w,
                            const float* __restrict__ right_w,
                            const float* __restrict__ gate_w) {
    int i = blockIdx.x * blockDim.x + threadIdx.x;
    if (i < Hn * Ln) { int h = i / Ln, l = i - h * Ln; g_outwT[i] = tf32rf(out_w[l * Hn + h]); }
    if (i < Ln * Dn) { int l = i / Dn, d = i - l * Dn; g_AwT[i] = tf32rf(A_w[d * Ln + l]);
                                                      g_BwT[i] = tf32rf(B_w[d * Ln + l]); }
    if (i < Dn * 512) {
        int k = i >> 9, n = i & 511;
        g_lrwT[i] = tf32rf(n < Hn ? left_w[(size_t)n * Dn + k]
                                  : right_w[(size_t)(n - Hn) * Dn + k]);
    }
    if (i < 2 * Dn * Dn) {
        int k = i / Dn, n = i - k * Dn;
        g_gwT[i] = tf32rf(gate_w[(size_t)n * (2 * Dn) + k]);
    }
}

// 4 float4 per thread (MLP=4)
__global__ void copy_init_kernel(const float* __restrict__ all_vecs,
                                 const float* __restrict__ span_vecs,
                                 float* __restrict__ outAll,
                                 float* __restrict__ outU) {
    const int stride = BND / 16;
    int i = blockIdx.x * blockDim.x + threadIdx.x;
    if (i < stride) {
#pragma unroll
        for (int e = 0; e < 4; e++) {
            int idx = i + e * stride;
            ((float4*)outAll)[idx] = ((const float4*)all_vecs)[idx];
        }
        if (i < BKD / 4) ((float4*)outU)[i] = ((const float4*)span_vecs)[i];
    }
}

// ---------------- proj split-K: partials for u @ [left_w|right_w]^T --------
// grid (4, 8, 3): m-tile 128, n-tile 64 over 512 cols, split z covers k [z*256,(z+1)*256)
// B staged from pre-transposed g_lrwT[k][n] via smem.
__global__ __launch_bounds__(256) void proj_kernel(const float* __restrict__ u) {
    __shared__ float As[128][36];
    __shared__ float Bs[32][72];
    const int tid = threadIdx.x;
    const int warp = tid >> 5, lane = tid & 31;
    const int wm = warp & 3, wn = warp >> 2;
    const int grp = lane >> 2, q = lane & 3;
    const int m0 = blockIdx.x * 128, n0 = blockIdx.y * 64;
    const int kBeg = blockIdx.z * 256, kEnd = kBeg + 256;
    const int fm = tid >> 1, fh = tid & 1;
    const int fn = tid & 63, fk = tid >> 6;
    float acc[2][4][4] = {};

    for (int kb = kBeg; kb < kEnd; kb += 32) {
        const float* src = u + (size_t)(m0 + fm) * Dn + kb + fh * 16;
#pragma unroll
        for (int e = 0; e < 4; e++) {
            float4 v = *(const float4*)(src + 4 * e);
            int c = fh * 16 + 4 * e;
            As[fm][c + 0] = tf32rf(v.x); As[fm][c + 1] = tf32rf(v.y);
            As[fm][c + 2] = tf32rf(v.z); As[fm][c + 3] = tf32rf(v.w);
        }
#pragma unroll
        for (int e = 0; e < 8; e++)
            Bs[fk * 8 + e][fn] = g_lrwT[(size_t)(kb + fk * 8 + e) * 512 + n0 + fn];
        __syncthreads();
#pragma unroll
        for (int k0 = 0; k0 < 32; k0 += 8) {
            uint32_t b0[4], b1[4];
#pragma unroll
            for (int ni = 0; ni < 4; ni++) {
                int n = wn * 32 + ni * 8 + grp;
                b0[ni] = __float_as_uint(Bs[k0 + q][n]);
                b1[ni] = __float_as_uint(Bs[k0 + q + 4][n]);
            }
#pragma unroll
            for (int mi = 0; mi < 2; mi++) {
                int mb = wm * 32 + mi * 16;
                uint32_t a0 = __float_as_uint(As[mb + grp][k0 + q]);
                uint32_t a1 = __float_as_uint(As[mb + 8 + grp][k0 + q]);
                uint32_t a2 = __float_as_uint(As[mb + grp][k0 + q + 4]);
                uint32_t a3 = __float_as_uint(As[mb + 8 + grp][k0 + q + 4]);
#pragma unroll
                for (int ni = 0; ni < 4; ni++)
                    mma8(acc[mi][ni], a0, a1, a2, a3, b0[ni], b1[ni]);
            }
        }
        __syncthreads();
    }
    float* dst = g_part[blockIdx.z];
#pragma unroll
    for (int mi = 0; mi < 2; mi++) {
        int r0 = m0 + wm * 32 + mi * 16 + grp;
#pragma unroll
        for (int ni = 0; ni < 4; ni++) {
            int c = n0 + wn * 32 + ni * 8 + 2 * q;
            dst[(size_t)r0 * 512 + c]           = acc[mi][ni][0];
            dst[(size_t)r0 * 512 + c + 1]       = acc[mi][ni][1];
            dst[(size_t)(r0 + 8) * 512 + c]     = acc[mi][ni][2];
            dst[(size_t)(r0 + 8) * 512 + c + 1] = acc[mi][ni][3];
        }
    }
}

__global__ void combine_proj_kernel(const float* __restrict__ left_b,
                                    const float* __restrict__ right_b) {
    int i = blockIdx.x * blockDim.x + threadIdx.x;   // 512*512
    if (i < 512 * 512) {
        int m = i >> 9, n = i & 511;
        float s = g_part[0][i] + g_part[1][i] + g_part[2][i];
        if (n < Hn) g_left [(size_t)m * Hn + n]      = s + left_b[n];
        else        g_right[(size_t)m * Hn + n - Hn] = s + right_b[n - Hn];
    }
}

// ---------------- fused pair-scorer + probs (R8 config, measured best) -----
// write_scores=0: probs only.  =1: scores only (final call).
// block = 256 threads = 8 warps (4 m x 2 n), block tile 128j x 64l, K=h(256)
// grid: (2, i=256, b=2)
__global__ __launch_bounds__(256) void scores_kernel(
        const int* __restrict__ span_begin, const int* __restrict__ span_end,
        const float* __restrict__ dist_emb, const float* __restrict__ out_b,
        const float* __restrict__ mask, float* __restrict__ scores,
        int write_scores) {
    __shared__ float As[128][36];
    __shared__ float oS[32][72];
    __shared__ float leftS[Hn];
    const int tid = threadIdx.x;
    const int warp = tid >> 5, lane = tid & 31;
    const int wm = warp & 3, wn = warp >> 2;
    const int grp = lane >> 2, q = lane & 3;
    const int b = blockIdx.z, i = blockIdx.y, j0 = blockIdx.x * 128;
    const int fm = tid >> 1, fh = tid & 1;
    const int fn = tid & 63, fk = tid >> 6;

    leftS[tid] = g_left[(size_t)(b * Kn + i) * Hn + tid];
    int dd = span_begin[b * Kn + j0 + fm] - span_end[b * Kn + i];
    int ad = abs(dd); const int bkt = ad > 63 ? 63 : ad;
    __syncthreads();

    float acc[2][4][4] = {};
    for (int hb = 0; hb < Hn; hb += 32) {
        const float* rsrc = g_right + (size_t)(b * Kn + j0 + fm) * Hn + hb + fh * 16;
        const float* dsrc = dist_emb + (size_t)bkt * Hn + hb + fh * 16;
#pragma unroll
        for (int e = 0; e < 4; e++) {
            float4 rv = *(const float4*)(rsrc + 4 * e);
            float4 dv = *(const float4*)(dsrc + 4 * e);
            int c = fh * 16 + 4 * e;
            float4 lv = *(const float4*)(&leftS[hb + c]);
            As[fm][c + 0] = tf32rf(fmaxf(lv.x + rv.x + dv.x, 0.f));
            As[fm][c + 1] = tf32rf(fmaxf(lv.y + rv.y + dv.y, 0.f));
            As[fm][c + 2] = tf32rf(fmaxf(lv.z + rv.z + dv.z, 0.f));
            As[fm][c + 3] = tf32rf(fmaxf(lv.w + rv.w + dv.w, 0.f));
        }
#pragma unroll
        for (int e = 0; e < 8; e++)
            oS[fk * 8 + e][fn] = g_outwT[(size_t)(hb + fk * 8 + e) * Ln + fn];
        __syncthreads();
#pragma unroll
        for (int k0 = 0; k0 < 32; k0 += 8) {
            uint32_t b0[4], b1[4];
#pragma unroll
            for (int ni = 0; ni < 4; ni++) {
                int n = wn * 32 + ni * 8 + grp;
                b0[ni] = __float_as_uint(oS[k0 + q][n]);
                b1[ni] = __float_as_uint(oS[k0 + q + 4][n]);
            }
#pragma unroll
            for (int mi = 0; mi < 2; mi++) {
                int mb = wm * 32 + mi * 16;
                uint32_t a0 = __float_as_uint(As[mb + grp][k0 + q]);
                uint32_t a1 = __float_as_uint(As[mb + 8 + grp][k0 + q]);
                uint32_t a2 = __float_as_uint(As[mb + grp][k0 + q + 4]);
                uint32_t a3 = __float_as_uint(As[mb + 8 + grp][k0 + q + 4]);
#pragma unroll
                for (int ni = 0; ni < 4; ni++)
                    mma8(acc[mi][ni], a0, a1, a2, a3, b0[ni], b1[ni]);
            }
        }
        __syncthreads();
    }
    float* scRow = scores + (size_t)(b * Kn + i) * (Kn * Ln);
    float* prRow = g_probs + (size_t)(b * Kn + i) * (Kn * Ln);
    const float* mkRow = mask + (size_t)(b * Kn + i) * Kn;
#pragma unroll
    for (int mi = 0; mi < 2; mi++) {
        int j0l = wm * 32 + mi * 16 + grp;
        float mk0 = mkRow[j0 + j0l], mk1 = mkRow[j0 + j0l + 8];
#pragma unroll
        for (int ni = 0; ni < 4; ni++) {
            int c = wn * 32 + ni * 8 + 2 * q;
#pragma unroll
            for (int e = 0; e < 2; e++) {
                float s0 = acc[mi][ni][e]     + out_b[c + e];
                float s1 = acc[mi][ni][2 + e] + out_b[c + e];
                if (write_scores) {
                    scRow[(size_t)(j0 + j0l) * Ln + c + e]     = s0;
                    scRow[(size_t)(j0 + j0l + 8) * Ln + c + e] = s1;
                } else {
                    prRow[(size_t)(j0 + j0l) * Ln + c + e]     = tf32rf(sigmoidf(s0) * mk0);
                    prRow[(size_t)(j0 + j0l + 8) * Ln + c + e] = tf32rf(sigmoidf(s1) * mk1);
                }
            }
        }
    }
}

// ---------------- context GEMMs: cp.async double-buffered, single-wave -----
// block = 256 threads = 8 warps (4m x 2n), block tile 256m x 64d.
// 6 UNEVEN k-splits (86,86,85,85,85,85 chunks of 512) -> grid 288 = one wave
// grid: (1, d-tile=12, z = b*12 + mode*6 + split)
#define CTXT_SMEM ((2 * 256 * 36 + 64 * 72) * 4)
__global__ __launch_bounds__(256, 2) void ctxt_kernel(const float* __restrict__ u) {
    extern __shared__ float dsm[];
    float* AsBase = dsm;
    float* wS     = dsm + 2 * 256 * 36;
    const int tid = threadIdx.x;
    const int warp = tid >> 5, lane = tid & 31;
    const int wm = warp & 3, wn = warp >> 2;
    const int grp = lane >> 2, q = lane & 3;
    const int z = blockIdx.z;
    const int b = z / 12, r12 = z % 12, mode = r12 / 6, split = r12 % 6;
    const int d0 = blockIdx.y * 64;
    const float* wT = (mode == 0) ? g_AwT : g_BwT;
    const float* probsB = g_probs + (size_t)b * Kn * Kn * Ln;
    const float* uB     = u       + (size_t)b * Kn * Dn;
    const int arow = tid >> 3, aq = tid & 7;

    int cn[4], dcol[4];
#pragma unroll
    for (int ni = 0; ni < 4; ni++) {
        cn[ni]   = wn * 32 + ni * 8 + grp;
        dcol[ni] = d0 + cn[ni];
    }

    {
        int l = tid >> 2, c16 = (tid & 3) * 16;
#pragma unroll
        for (int e = 0; e < 4; e++) {
            float4 v = *(const float4*)&wT[(size_t)l * Dn + d0 + c16 + 4 * e];
            int c = c16 + 4 * e;
            wS[l * 72 + c + 0] = v.x; wS[l * 72 + c + 1] = v.y;
            wS[l * 72 + c + 2] = v.z; wS[l * 72 + c + 3] = v.w;
        }
    }

    // uneven split over 512 chunks of 32 r
    const int begChunk = split * 85 + (split < 2 ? split : 2);
    const int NC       = 85 + (split < 2 ? 1 : 0);
    const int rBeg     = begChunk * 32;

    auto issueA = [&](int c, int buf) {
        int rb = rBeg + c * 32;
        int other = rb >> 6, l0 = rb & 63;
        float* dstBase = AsBase + buf * 9216;
#pragma unroll
        for (int p = 0; p < 8; p++) {
            int m = p * 32 + arow;
            const float* src = (mode == 0)
                ? &probsB[((size_t)other * Kn + m) * Ln + l0 + aq * 4]
                : &probsB[((size_t)m * Kn + other) * Ln + l0 + aq * 4];
            uint32_t daddr = (uint32_t)__cvta_generic_to_shared(dstBase + m * 36 + aq * 4);
            cp16(daddr, src);
        }
    };

    issueA(0, 0);
    asm volatile("cp.async.commit_group;\n");
    __syncthreads();

    float acc[4][4][4] = {};
    float uval[4], unext[4];
    {
        int o0 = rBeg >> 6;
#pragma unroll
        for (int ni = 0; ni < 4; ni++) uval[ni] = uB[(size_t)o0 * Dn + dcol[ni]];
    }

    for (int c = 0; c < NC; c++) {
        if (c + 1 < NC) {
            issueA(c + 1, (c + 1) & 1);
            int on = (rBeg + (c + 1) * 32) >> 6;
#pragma unroll
            for (int ni = 0; ni < 4; ni++) unext[ni] = uB[(size_t)on * Dn + dcol[ni]];
        }
        asm volatile("cp.async.commit_group;\n");
        if (c + 1 < NC) asm volatile("cp.async.wait_group 1;\n");
        else            asm volatile("cp.async.wait_group 0;\n");
        __syncthreads();

        const float* AsBuf = AsBase + (c & 1) * 9216;
        const int l0 = (rBeg + c * 32) & 63;
#pragma unroll
        for (int k0 = 0; k0 < 32; k0 += 8) {
            uint32_t b0[4], b1[4];
#pragma unroll
            for (int ni = 0; ni < 4; ni++) {
                float w0 = wS[(l0 + k0 + q) * 72 + cn[ni]];
                float w1 = wS[(l0 + k0 + q + 4) * 72 + cn[ni]];
                b0[ni] = __float_as_uint(uval[ni] * w0);   // mma reads tf32 bits (RZ)
                b1[ni] = __float_as_uint(uval[ni] * w1);
            }
#pragma unroll
            for (int mi = 0; mi < 4; mi++) {
                int mb = wm * 64 + mi * 16;
                uint32_t a0 = __float_as_uint(AsBuf[(mb + grp) * 36 + k0 + q]);
                uint32_t a1 = __float_as_uint(AsBuf[(mb + 8 + grp) * 36 + k0 + q]);
                uint32_t a2 = __float_as_uint(AsBuf[(mb + grp) * 36 + k0 + q + 4]);
                uint32_t a3 = __float_as_uint(AsBuf[(mb + 8 + grp) * 36 + k0 + q + 4]);
#pragma unroll
                for (int ni = 0; ni < 4; ni++)
                    mma8(acc[mi][ni], a0, a1, a2, a3, b0[ni], b1[ni]);
            }
        }
        __syncthreads();
#pragma unroll
        for (int ni = 0; ni < 4; ni++) uval[ni] = unext[ni];
    }

    float* dst = g_part[mode * 6 + split];
#pragma unroll
    for (int mi = 0; mi < 4; mi++) {
        int row = wm * 64 + mi * 16 + grp;
#pragma unroll
        for (int ni = 0; ni < 4; ni++) {
            int c = d0 + wn * 32 + ni * 8 + 2 * q;
            *(float2*)&dst[((size_t)b * Kn + row) * Dn + c] =
                make_float2(acc[mi][ni][0], acc[mi][ni][1]);
            *(float2*)&dst[((size_t)b * Kn + row + 8) * Dn + c] =
                make_float2(acc[mi][ni][2], acc[mi][ni][3]);
        }
    }
}

__global__ void combine_kernel(const float* __restrict__ slen) {
    int i = blockIdx.x * blockDim.x + threadIdx.x;   // float4 index
    if (i < BKD / 4) {
        int b = (i * 4) / (Kn * Dn);
        float4 s = make_float4(0.f, 0.f, 0.f, 0.f);
#pragma unroll
        for (int p = 0; p < 12; p++) {
            float4 v = *(const float4*)&g_part[p][i * 4];
            s.x += v.x; s.y += v.y; s.z += v.z; s.w += v.w;
        }
        float inv = 1.0f / slen[b];
        s.x *= inv; s.y *= inv; s.z *= inv; s.w *= inv;
        *(float4*)&g_c[i * 4] = s;
    }
}

// ---------------- gate split-K: partials of [u|c] @ gate_w^T ---------------
// grid (4, 12, 4): split z covers k [z*384,(z+1)*384); partials -> slots 12..15
// B staged from pre-transposed g_gwT[k][n] via smem.
__global__ __launch_bounds__(256) void gate_kernel(const float* __restrict__ u) {
    __shared__ float As[128][36];
    __shared__ float Bs[32][72];
    const int tid = threadIdx.x;
    const int warp = tid >> 5, lane = tid & 31;
    const int wm = warp & 3, wn = warp >> 2;
    const int grp = lane >> 2, q = lane & 3;
    const int m0 = blockIdx.x * 128, n0 = blockIdx.y * 64;
    const int kBeg = blockIdx.z * 384, kEnd = kBeg + 384;
    const int fm = tid >> 1, fh = tid & 1;
    const int fn = tid & 63, fk = tid >> 6;
    float acc[2][4][4] = {};

    for (int kb = kBeg; kb < kEnd; kb += 32) {
        const float* src = (kb < Dn)
            ? u   + (size_t)(m0 + fm) * Dn + kb + fh * 16
            : g_c + (size_t)(m0 + fm) * Dn + (kb - Dn) + fh * 16;
#pragma unroll
        for (int e = 0; e < 4; e++) {
            float4 v = *(const float4*)(src + 4 * e);
            int c = fh * 16 + 4 * e;
            As[fm][c + 0] = tf32rf(v.x); As[fm][c + 1] = tf32rf(v.y);
            As[fm][c + 2] = tf32rf(v.z); As[fm][c + 3] = tf32rf(v.w);
        }
#pragma unroll
        for (int e = 0; e < 8; e++)
            Bs[fk * 8 + e][fn] = g_gwT[(size_t)(kb + fk * 8 + e) * Dn + n0 + fn];
        __syncthreads();
#pragma unroll
        for (int k0 = 0; k0 < 32; k0 += 8) {
            uint32_t b0[4], b1[4];
#pragma unroll
            for (int ni = 0; ni < 4; ni++) {
                int n = wn * 32 + ni * 8 + grp;
                b0[ni] = __float_as_uint(Bs[k0 + q][n]);
                b1[ni] = __float_as_uint(Bs[k0 + q + 4][n]);
            }
#pragma unroll
            for (int mi = 0; mi < 2; mi++) {
                int mb = wm * 32 + mi * 16;
                uint32_t a0 = __float_as_uint(As[mb + grp][k0 + q]);
                uint32_t a1 = __float_as_uint(As[mb + 8 + grp][k0 + q]);
                uint32_t a2 = __float_as_uint(As[mb + grp][k0 + q + 4]);
                uint32_t a3 = __float_as_uint(As[mb + 8 + grp][k0 + q + 4]);
#pragma unroll
                for (int ni = 0; ni < 4; ni++)
                    mma8(acc[mi][ni], a0, a1, a2, a3, b0[ni], b1[ni]);
            }
        }
        __syncthreads();
    }
    float* dst = g_part[12 + blockIdx.z];
#pragma unroll
    for (int mi = 0; mi < 2; mi++) {
        int r0 = m0 + wm * 32 + mi * 16 + grp;
#pragma unroll
        for (int ni = 0; ni < 4; ni++) {
            int c = n0 + wn * 32 + ni * 8 + 2 * q;
            dst[(size_t)r0 * Dn + c]           = acc[mi][ni][0];
            dst[(size_t)r0 * Dn + c + 1]       = acc[mi][ni][1];
            dst[(size_t)(r0 + 8) * Dn + c]     = acc[mi][ni][2];
            dst[(size_t)(r0 + 8) * Dn + c + 1] = acc[mi][ni][3];
        }
    }
}

__global__ void combine_gate_update_kernel(const float* __restrict__ gate_b,
                                           float* __restrict__ u) {
    int i = blockIdx.x * blockDim.x + threadIdx.x;   // float4 index
    if (i < BKD / 4) {
        int n = (i * 4) % Dn;
        float4 s3 = *(const float4*)&g_part[12][i * 4];
        float4 s4 = *(const float4*)&g_part[13][i * 4];
        float4 s5 = *(const float4*)&g_part[14][i * 4];
        float4 s6 = *(const float4*)&g_part[15][i * 4];
        float4 gb = *(const float4*)&gate_b[n];
        float4 uv = *(const float4*)&u[i * 4];
        float4 cv = *(const float4*)&g_c[i * 4];
        float g0 = sigmoidf(s3.x + s4.x + s5.x + s6.x + gb.x);
        float g1 = sigmoidf(s3.y + s4.y + s5.y + s6.y + gb.y);
        float g2 = sigmoidf(s3.z + s4.z + s5.z + s6.z + gb.z);
        float g3 = sigmoidf(s3.w + s4.w + s5.w + s6.w + gb.w);
        float4 o;
        o.x = g0 * uv.x + (1.0f - g0) * cv.x;
        o.y = g1 * uv.y + (1.0f - g1) * cv.y;
        o.z = g2 * uv.z + (1.0f - g2) * cv.z;
        o.w = g3 * uv.w + (1.0f - g3) * cv.w;
        *(float4*)&u[i * 4] = o;
    }
}

__global__ void scatter_kernel(const int* __restrict__ prune, const float* __restrict__ slen,
                               const float* __restrict__ u, float* __restrict__ outAll) {
    int i = blockIdx.x * blockDim.x + threadIdx.x;   // float4 index
    if (i < BKD / 4) {
        int idx = i * 4;
        int d = idx % Dn, bk = idx / Dn, b = bk / Kn, k = bk % Kn;
        if ((float)k < slen[b]) {
            int row = prune[bk];
            *(float4*)&outAll[((size_t)b * Nn + row) * Dn + d] = *(const float4*)&u[idx];
        }
    }
}

// ---------------- driver ---------------------------------------------------
extern "C" void kernel_launch(void* const* d_in, const int* in_sizes, int n_in,
                              void* d_out, int out_size) {
    (void)in_sizes; (void)n_in; (void)out_size;
    const float* all_vecs  = (const float*)d_in[0];
    const float* span_vecs = (const float*)d_in[1];
    const int*   span_beg  = (const int*)  d_in[2];
    const int*   span_end  = (const int*)  d_in[3];
    const float* mask      = (const float*)d_in[4];
    const float* slen      = (const float*)d_in[5];
    const int*   prune     = (const int*)  d_in[6];
    const float* left_w    = (const float*)d_in[7];
    const float* left_b    = (const float*)d_in[8];
    const float* right_w   = (const float*)d_in[9];
    const float* right_b   = (const float*)d_in[10];
    const float* dist_emb  = (const float*)d_in[11];
    const float* out_w     = (const float*)d_in[12];
    const float* out_b     = (const float*)d_in[13];
    const float* A_w       = (const float*)d_in[14];
    const float* B_w       = (const float*)d_in[15];
    const float* gate_w    = (const float*)d_in[16];
    const float* gate_b    = (const float*)d_in[17];

    float* outAll = (float*)d_out;           // [B,N,D]
    float* outU   = outAll + BND;            // [B,K,D]
    float* outS   = outU + BKD;              // [B,K,K,L]

    static int attr_done = 0;
    if (!attr_done) {
        cudaFuncSetAttribute(ctxt_kernel,
                             cudaFuncAttributeMaxDynamicSharedMemorySize, CTXT_SMEM);
        attr_done = 1;
    }

    prep_kernel<<<(2 * Dn * Dn + 255) / 256, 256>>>(out_w, A_w, B_w, left_w, right_w, gate_w);
    copy_init_kernel<<<(BND / 16 + 255) / 256, 256>>>(all_vecs, span_vecs, outAll, outU);

    proj_kernel<<<dim3(4, 8, 3), 256>>>(outU);
    combine_proj_kernel<<<(512 * 512 + 255) / 256, 256>>>(left_b, right_b);
    scores_kernel<<<dim3(2, Kn, Bn), 256>>>(span_beg, span_end, dist_emb, out_b, mask, outS, 0);

    for (int t = 0; t < 3; t++) {
        ctxt_kernel<<<dim3(1, 12, 24), 256, CTXT_SMEM>>>(outU);
        combine_kernel<<<(BKD / 4 + 255) / 256, 256>>>(slen);
        gate_kernel<<<dim3(4, 12, 4), 256>>>(outU);
        combine_gate_update_kernel<<<(BKD / 4 + 255) / 256, 256>>>(gate_b, outU);
        proj_kernel<<<dim3(4, 8, 3), 256>>>(outU);
        combine_proj_kernel<<<(512 * 512 + 255) / 256, 256>>>(left_b, right_b);
        scores_kernel<<<dim3(2, Kn, Bn), 256>>>(span_beg, span_end, dist_emb, out_b, mask,
                                                outS, t == 2 ? 1 : 0);
    }

    scatter_kernel<<<(BKD / 4 + 255) / 256, 256>>>(prune, slen, outU, outAll);
}

// round 16
// speedup vs baseline: 1.1921x; 1.0264x over previous
#include <cuda_runtime.h>
#include <cstdint>

#define Bn 2
#define Nn 2048
#define Kn 256
#define Dn 768
#define Hn 256
#define Ln 64
#define BND (Bn*Nn*Dn)
#define BKD (Bn*Kn*Dn)
#define BKH (Bn*Kn*Hn)
#define BKKL ((size_t)Bn*Kn*Kn*Ln)

// ---------------- scratch (device globals; no allocations allowed) ----------
__device__ float g_left [BKH];
__device__ float g_right[BKH];
__device__ float g_outwT[Hn*Ln];      // [h][l], tf32-rounded
__device__ float g_AwT  [Ln*Dn];      // [l][d], tf32-rounded
__device__ float g_BwT  [Ln*Dn];      // [l][d], tf32-rounded
__device__ float g_lrwT [Dn*512];     // [k][n] (n<256: left, else right), tf32-rounded
__device__ float g_gwT  [2*Dn*Dn];    // [k][n], tf32-rounded gate_w^T
__device__ float g_probs[BKKL];       // sigmoid(score)*mask, tf32-rounded
__device__ float g_part [16][BKD];    // ctxt partials (0..11); proj reuses 0..2, gate 12..15
__device__ float g_c    [BKD];

__device__ __forceinline__ float sigmoidf(float x) {
    return 1.0f / (1.0f + __expf(-x));
}
__device__ __forceinline__ uint32_t tf32r(float x) {
    uint32_t u; asm("cvt.rna.tf32.f32 %0, %1;" : "=r"(u) : "f"(x)); return u;
}
__device__ __forceinline__ float tf32rf(float x) {
    return __uint_as_float(tf32r(x));
}
__device__ __forceinline__ void mma8(float c[4], uint32_t a0, uint32_t a1, uint32_t a2,
                                     uint32_t a3, uint32_t b0, uint32_t b1) {
    asm("mma.sync.aligned.m16n8k8.row.col.f32.tf32.tf32.f32 "
        "{%0,%1,%2,%3},{%4,%5,%6,%7},{%8,%9},{%0,%1,%2,%3};"
        : "+f"(c[0]), "+f"(c[1]), "+f"(c[2]), "+f"(c[3])
        : "r"(a0), "r"(a1), "r"(a2), "r"(a3), "r"(b0), "r"(b1));
}
__device__ __forceinline__ void cp16(uint32_t daddr, const void* src) {
    asm volatile("cp.async.cg.shared.global [%0], [%1], 16;\n" :: "r"(daddr), "l"(src));
}

// ---------------- prep: tf32-rounded weight transposes ---------------------
__global__ void prep_kernel(const float* __restrict__ out_w,
                            const float* __restrict__ A_w,
                            const float* __restrict__ B_w,
                            const float* __restrict__ left_w,
                            const float* __restrict__ right_w,
                            const float* __restrict__ gate_w) {
    int i = blockIdx.x * blockDim.x + threadIdx.x;
    if (i < Hn * Ln) { int h = i / Ln, l = i - h * Ln; g_outwT[i] = tf32rf(out_w[l * Hn + h]); }
    if (i < Ln * Dn) { int l = i / Dn, d = i - l * Dn; g_AwT[i] = tf32rf(A_w[d * Ln + l]);
                                                      g_BwT[i] = tf32rf(B_w[d * Ln + l]); }
    if (i < Dn * 512) {
        int k = i >> 9, n = i & 511;
        g_lrwT[i] = tf32rf(n < Hn ? left_w[(size_t)n * Dn + k]
                                  : right_w[(size_t)(n - Hn) * Dn + k]);
    }
    if (i < 2 * Dn * Dn) {
        int k = i / Dn, n = i - k * Dn;
        g_gwT[i] = tf32rf(gate_w[(size_t)n * (2 * Dn) + k]);
    }
}

// 4 float4 per thread (MLP=4)
__global__ void copy_init_kernel(const float* __restrict__ all_vecs,
                                 const float* __restrict__ span_vecs,
                                 float* __restrict__ outAll,
                                 float* __restrict__ outU) {
    const int stride = BND / 16;
    int i = blockIdx.x * blockDim.x + threadIdx.x;
    if (i < stride) {
#pragma unroll
        for (int e = 0; e < 4; e++) {
            int idx = i + e * stride;
            ((float4*)outAll)[idx] = ((const float4*)all_vecs)[idx];
        }
        if (i < BKD / 4) ((float4*)outU)[i] = ((const float4*)span_vecs)[i];
    }
}

// ---------------- proj split-K: partials for u @ [left_w|right_w]^T --------
// grid (4, 8, 3): m-tile 128, n-tile 64 over 512 cols, split z covers k [z*256,(z+1)*256)
__global__ __launch_bounds__(256) void proj_kernel(const float* __restrict__ u) {
    __shared__ float As[128][36];
    __shared__ float Bs[32][72];
    const int tid = threadIdx.x;
    const int warp = tid >> 5, lane = tid & 31;
    const int wm = warp & 3, wn = warp >> 2;
    const int grp = lane >> 2, q = lane & 3;
    const int m0 = blockIdx.x * 128, n0 = blockIdx.y * 64;
    const int kBeg = blockIdx.z * 256, kEnd = kBeg + 256;
    const int fm = tid >> 1, fh = tid & 1;
    const int fn = tid & 63, fk = tid >> 6;
    float acc[2][4][4] = {};

    for (int kb = kBeg; kb < kEnd; kb += 32) {
        const float* src = u + (size_t)(m0 + fm) * Dn + kb + fh * 16;
#pragma unroll
        for (int e = 0; e < 4; e++) {
            float4 v = *(const float4*)(src + 4 * e);
            int c = fh * 16 + 4 * e;
            As[fm][c + 0] = tf32rf(v.x); As[fm][c + 1] = tf32rf(v.y);
            As[fm][c + 2] = tf32rf(v.z); As[fm][c + 3] = tf32rf(v.w);
        }
#pragma unroll
        for (int e = 0; e < 8; e++)
            Bs[fk * 8 + e][fn] = g_lrwT[(size_t)(kb + fk * 8 + e) * 512 + n0 + fn];
        __syncthreads();
#pragma unroll
        for (int k0 = 0; k0 < 32; k0 += 8) {
            uint32_t b0[4], b1[4];
#pragma unroll
            for (int ni = 0; ni < 4; ni++) {
                int n = wn * 32 + ni * 8 + grp;
                b0[ni] = __float_as_uint(Bs[k0 + q][n]);
                b1[ni] = __float_as_uint(Bs[k0 + q + 4][n]);
            }
#pragma unroll
            for (int mi = 0; mi < 2; mi++) {
                int mb = wm * 32 + mi * 16;
                uint32_t a0 = __float_as_uint(As[mb + grp][k0 + q]);
                uint32_t a1 = __float_as_uint(As[mb + 8 + grp][k0 + q]);
                uint32_t a2 = __float_as_uint(As[mb + grp][k0 + q + 4]);
                uint32_t a3 = __float_as_uint(As[mb + 8 + grp][k0 + q + 4]);
#pragma unroll
                for (int ni = 0; ni < 4; ni++)
                    mma8(acc[mi][ni], a0, a1, a2, a3, b0[ni], b1[ni]);
            }
        }
        __syncthreads();
    }
    float* dst = g_part[blockIdx.z];
#pragma unroll
    for (int mi = 0; mi < 2; mi++) {
        int r0 = m0 + wm * 32 + mi * 16 + grp;
#pragma unroll
        for (int ni = 0; ni < 4; ni++) {
            int c = n0 + wn * 32 + ni * 8 + 2 * q;
            dst[(size_t)r0 * 512 + c]           = acc[mi][ni][0];
            dst[(size_t)r0 * 512 + c + 1]       = acc[mi][ni][1];
            dst[(size_t)(r0 + 8) * 512 + c]     = acc[mi][ni][2];
            dst[(size_t)(r0 + 8) * 512 + c + 1] = acc[mi][ni][3];
        }
    }
}

__global__ void combine_proj_kernel(const float* __restrict__ left_b,
                                    const float* __restrict__ right_b) {
    int i = blockIdx.x * blockDim.x + threadIdx.x;   // 512*512
    if (i < 512 * 512) {
        int m = i >> 9, n = i & 511;
        float s = g_part[0][i] + g_part[1][i] + g_part[2][i];
        if (n < Hn) g_left [(size_t)m * Hn + n]      = s + left_b[n];
        else        g_right[(size_t)m * Hn + n - Hn] = s + right_b[n - Hn];
    }
}

// ---------------- fused pair-scorer + probs (R8 config, measured best) -----
// write_scores=0: probs only.  =1: scores only (final call).
// block = 256 threads = 8 warps (4 m x 2 n), block tile 128j x 64l, K=h(256)
// grid: (2, i=256, b=2)
__global__ __launch_bounds__(256) void scores_kernel(
        const int* __restrict__ span_begin, const int* __restrict__ span_end,
        const float* __restrict__ dist_emb, const float* __restrict__ out_b,
        const float* __restrict__ mask, float* __restrict__ scores,
        int write_scores) {
    __shared__ float As[128][36];
    __shared__ float oS[32][72];
    __shared__ float leftS[Hn];
    const int tid = threadIdx.x;
    const int warp = tid >> 5, lane = tid & 31;
    const int wm = warp & 3, wn = warp >> 2;
    const int grp = lane >> 2, q = lane & 3;
    const int b = blockIdx.z, i = blockIdx.y, j0 = blockIdx.x * 128;
    const int fm = tid >> 1, fh = tid & 1;
    const int fn = tid & 63, fk = tid >> 6;

    leftS[tid] = g_left[(size_t)(b * Kn + i) * Hn + tid];
    int dd = span_begin[b * Kn + j0 + fm] - span_end[b * Kn + i];
    int ad = abs(dd); const int bkt = ad > 63 ? 63 : ad;
    __syncthreads();

    float acc[2][4][4] = {};
    for (int hb = 0; hb < Hn; hb += 32) {
        const float* rsrc = g_right + (size_t)(b * Kn + j0 + fm) * Hn + hb + fh * 16;
        const float* dsrc = dist_emb + (size_t)bkt * Hn + hb + fh * 16;
#pragma unroll
        for (int e = 0; e < 4; e++) {
            float4 rv = *(const float4*)(rsrc + 4 * e);
            float4 dv = *(const float4*)(dsrc + 4 * e);
            int c = fh * 16 + 4 * e;
            float4 lv = *(const float4*)(&leftS[hb + c]);
            As[fm][c + 0] = tf32rf(fmaxf(lv.x + rv.x + dv.x, 0.f));
            As[fm][c + 1] = tf32rf(fmaxf(lv.y + rv.y + dv.y, 0.f));
            As[fm][c + 2] = tf32rf(fmaxf(lv.z + rv.z + dv.z, 0.f));
            As[fm][c + 3] = tf32rf(fmaxf(lv.w + rv.w + dv.w, 0.f));
        }
#pragma unroll
        for (int e = 0; e < 8; e++)
            oS[fk * 8 + e][fn] = g_outwT[(size_t)(hb + fk * 8 + e) * Ln + fn];
        __syncthreads();
#pragma unroll
        for (int k0 = 0; k0 < 32; k0 += 8) {
            uint32_t b0[4], b1[4];
#pragma unroll
            for (int ni = 0; ni < 4; ni++) {
                int n = wn * 32 + ni * 8 + grp;
                b0[ni] = __float_as_uint(oS[k0 + q][n]);
                b1[ni] = __float_as_uint(oS[k0 + q + 4][n]);
            }
#pragma unroll
            for (int mi = 0; mi < 2; mi++) {
                int mb = wm * 32 + mi * 16;
                uint32_t a0 = __float_as_uint(As[mb + grp][k0 + q]);
                uint32_t a1 = __float_as_uint(As[mb + 8 + grp][k0 + q]);
                uint32_t a2 = __float_as_uint(As[mb + grp][k0 + q + 4]);
                uint32_t a3 = __float_as_uint(As[mb + 8 + grp][k0 + q + 4]);
#pragma unroll
                for (int ni = 0; ni < 4; ni++)
                    mma8(acc[mi][ni], a0, a1, a2, a3, b0[ni], b1[ni]);
            }
        }
        __syncthreads();
    }
    float* scRow = scores + (size_t)(b * Kn + i) * (Kn * Ln);
    float* prRow = g_probs + (size_t)(b * Kn + i) * (Kn * Ln);
    const float* mkRow = mask + (size_t)(b * Kn + i) * Kn;
#pragma unroll
    for (int mi = 0; mi < 2; mi++) {
        int j0l = wm * 32 + mi * 16 + grp;
        float mk0 = mkRow[j0 + j0l], mk1 = mkRow[j0 + j0l + 8];
#pragma unroll
        for (int ni = 0; ni < 4; ni++) {
            int c = wn * 32 + ni * 8 + 2 * q;
#pragma unroll
            for (int e = 0; e < 2; e++) {
                float s0 = acc[mi][ni][e]     + out_b[c + e];
                float s1 = acc[mi][ni][2 + e] + out_b[c + e];
                if (write_scores) {
                    scRow[(size_t)(j0 + j0l) * Ln + c + e]     = s0;
                    scRow[(size_t)(j0 + j0l + 8) * Ln + c + e] = s1;
                } else {
                    prRow[(size_t)(j0 + j0l) * Ln + c + e]     = tf32rf(sigmoidf(s0) * mk0);
                    prRow[(size_t)(j0 + j0l + 8) * Ln + c + e] = tf32rf(sigmoidf(s1) * mk1);
                }
            }
        }
    }
}

// ---------------- context GEMMs: wide d-tile (128), 512 threads ------------
// block = 512 threads = 16 warps (4m x 4n), block tile 256m x 128d.
// 6 UNEVEN k-splits (86,86,85,85,85,85 chunks of 512).
// grid: (1, d-tile=6, z = b*12 + mode*6 + split) = 144 blocks = one wave @1/SM
#define CTXT_SMEM ((2 * 256 * 36 + 64 * 136) * 4)
__global__ __launch_bounds__(512, 1) void ctxt_kernel(const float* __restrict__ u) {
    extern __shared__ float dsm[];
    float* AsBase = dsm;                   // 2 * 9216
    float* wS     = dsm + 2 * 256 * 36;    // 64 * 136
    const int tid = threadIdx.x;
    const int warp = tid >> 5, lane = tid & 31;
    const int wm = warp & 3, wn = warp >> 2;      // wn 0..3
    const int grp = lane >> 2, q = lane & 3;
    const int z = blockIdx.z;
    const int b = z / 12, r12 = z % 12, mode = r12 / 6, split = r12 % 6;
    const int d0 = blockIdx.y * 128;
    const float* wT = (mode == 0) ? g_AwT : g_BwT;
    const float* probsB = g_probs + (size_t)b * Kn * Kn * Ln;
    const float* uB     = u       + (size_t)b * Kn * Dn;
    const int arow = tid >> 3, aq = tid & 7;      // A fill: 64 rows x 8 quads / pass

    int cn[4], dcol[4];
#pragma unroll
    for (int ni = 0; ni < 4; ni++) {
        cn[ni]   = wn * 32 + ni * 8 + grp;
        dcol[ni] = d0 + cn[ni];
    }

    // stage weight slice wS[64 l][128 d] once
    {
        int l = tid >> 3;                  // 0..63
#pragma unroll
        for (int e = 0; e < 4; e++) {
            int c = aq * 16 + 4 * e;
            float4 v = *(const float4*)&wT[(size_t)l * Dn + d0 + c];
            wS[l * 136 + c + 0] = v.x; wS[l * 136 + c + 1] = v.y;
            wS[l * 136 + c + 2] = v.z; wS[l * 136 + c + 3] = v.w;
        }
    }

    // uneven split over 512 chunks of 32 r
    const int begChunk = split * 85 + (split < 2 ? split : 2);
    const int NC       = 85 + (split < 2 ? 1 : 0);
    const int rBeg     = begChunk * 32;

    auto issueA = [&](int c, int buf) {
        int rb = rBeg + c * 32;
        int other = rb >> 6, l0 = rb & 63;
        float* dstBase = AsBase + buf * 9216;
#pragma unroll
        for (int p = 0; p < 4; p++) {
            int m = p * 64 + arow;
            const float* src = (mode == 0)
                ? &probsB[((size_t)other * Kn + m) * Ln + l0 + aq * 4]
                : &probsB[((size_t)m * Kn + other) * Ln + l0 + aq * 4];
            uint32_t daddr = (uint32_t)__cvta_generic_to_shared(dstBase + m * 36 + aq * 4);
            cp16(daddr, src);
        }
    };

    issueA(0, 0);
    asm volatile("cp.async.commit_group;\n");
    __syncthreads();

    float acc[4][4][4] = {};
    float uval[4], unext[4];
    {
        int o0 = rBeg >> 6;
#pragma unroll
        for (int ni = 0; ni < 4; ni++) uval[ni] = uB[(size_t)o0 * Dn + dcol[ni]];
    }

    for (int c = 0; c < NC; c++) {
        if (c + 1 < NC) {
            issueA(c + 1, (c + 1) & 1);
            int on = (rBeg + (c + 1) * 32) >> 6;
#pragma unroll
            for (int ni = 0; ni < 4; ni++) unext[ni] = uB[(size_t)on * Dn + dcol[ni]];
        }
        asm volatile("cp.async.commit_group;\n");
        if (c + 1 < NC) asm volatile("cp.async.wait_group 1;\n");
        else            asm volatile("cp.async.wait_group 0;\n");
        __syncthreads();

        const float* AsBuf = AsBase + (c & 1) * 9216;
        const int l0 = (rBeg + c * 32) & 63;
#pragma unroll
        for (int k0 = 0; k0 < 32; k0 += 8) {
            uint32_t b0[4], b1[4];
#pragma unroll
            for (int ni = 0; ni < 4; ni++) {
                float w0 = wS[(l0 + k0 + q) * 136 + cn[ni]];
                float w1 = wS[(l0 + k0 + q + 4) * 136 + cn[ni]];
                b0[ni] = __float_as_uint(uval[ni] * w0);   // mma reads tf32 bits (RZ)
                b1[ni] = __float_as_uint(uval[ni] * w1);
            }
#pragma unroll
            for (int mi = 0; mi < 4; mi++) {
                int mb = wm * 64 + mi * 16;
                uint32_t a0 = __float_as_uint(AsBuf[(mb + grp) * 36 + k0 + q]);
                uint32_t a1 = __float_as_uint(AsBuf[(mb + 8 + grp) * 36 + k0 + q]);
                uint32_t a2 = __float_as_uint(AsBuf[(mb + grp) * 36 + k0 + q + 4]);
                uint32_t a3 = __float_as_uint(AsBuf[(mb + 8 + grp) * 36 + k0 + q + 4]);
#pragma unroll
                for (int ni = 0; ni < 4; ni++)
                    mma8(acc[mi][ni], a0, a1, a2, a3, b0[ni], b1[ni]);
            }
        }
        __syncthreads();
#pragma unroll
        for (int ni = 0; ni < 4; ni++) uval[ni] = unext[ni];
    }

    float* dst = g_part[mode * 6 + split];
#pragma unroll
    for (int mi = 0; mi < 4; mi++) {
        int row = wm * 64 + mi * 16 + grp;
#pragma unroll
        for (int ni = 0; ni < 4; ni++) {
            int c = d0 + wn * 32 + ni * 8 + 2 * q;
            *(float2*)&dst[((size_t)b * Kn + row) * Dn + c] =
                make_float2(acc[mi][ni][0], acc[mi][ni][1]);
            *(float2*)&dst[((size_t)b * Kn + row + 8) * Dn + c] =
                make_float2(acc[mi][ni][2], acc[mi][ni][3]);
        }
    }
}

__global__ void combine_kernel(const float* __restrict__ slen) {
    int i = blockIdx.x * blockDim.x + threadIdx.x;   // float4 index
    if (i < BKD / 4) {
        int b = (i * 4) / (Kn * Dn);
        float4 s = make_float4(0.f, 0.f, 0.f, 0.f);
#pragma unroll
        for (int p = 0; p < 12; p++) {
            float4 v = *(const float4*)&g_part[p][i * 4];
            s.x += v.x; s.y += v.y; s.z += v.z; s.w += v.w;
        }
        float inv = 1.0f / slen[b];
        s.x *= inv; s.y *= inv; s.z *= inv; s.w *= inv;
        *(float4*)&g_c[i * 4] = s;
    }
}

// ---------------- gate split-K: partials of [u|c] @ gate_w^T ---------------
// grid (4, 12, 4): split z covers k [z*384,(z+1)*384); partials -> slots 12..15
__global__ __launch_bounds__(256) void gate_kernel(const float* __restrict__ u) {
    __shared__ float As[128][36];
    __shared__ float Bs[32][72];
    const int tid = threadIdx.x;
    const int warp = tid >> 5, lane = tid & 31;
    const int wm = warp & 3, wn = warp >> 2;
    const int grp = lane >> 2, q = lane & 3;
    const int m0 = blockIdx.x * 128, n0 = blockIdx.y * 64;
    const int kBeg = blockIdx.z * 384, kEnd = kBeg + 384;
    const int fm = tid >> 1, fh = tid & 1;
    const int fn = tid & 63, fk = tid >> 6;
    float acc[2][4][4] = {};

    for (int kb = kBeg; kb < kEnd; kb += 32) {
        const float* src = (kb < Dn)
            ? u   + (size_t)(m0 + fm) * Dn + kb + fh * 16
            : g_c + (size_t)(m0 + fm) * Dn + (kb - Dn) + fh * 16;
#pragma unroll
        for (int e = 0; e < 4; e++) {
            float4 v = *(const float4*)(src + 4 * e);
            int c = fh * 16 + 4 * e;
            As[fm][c + 0] = tf32rf(v.x); As[fm][c + 1] = tf32rf(v.y);
            As[fm][c + 2] = tf32rf(v.z); As[fm][c + 3] = tf32rf(v.w);
        }
#pragma unroll
        for (int e = 0; e < 8; e++)
            Bs[fk * 8 + e][fn] = g_gwT[(size_t)(kb + fk * 8 + e) * Dn + n0 + fn];
        __syncthreads();
#pragma unroll
        for (int k0 = 0; k0 < 32; k0 += 8) {
            uint32_t b0[4], b1[4];
#pragma unroll
            for (int ni = 0; ni < 4; ni++) {
                int n = wn * 32 + ni * 8 + grp;
                b0[ni] = __float_as_uint(Bs[k0 + q][n]);
                b1[ni] = __float_as_uint(Bs[k0 + q + 4][n]);
            }
#pragma unroll
            for (int mi = 0; mi < 2; mi++) {
                int mb = wm * 32 + mi * 16;
                uint32_t a0 = __float_as_uint(As[mb + grp][k0 + q]);
                uint32_t a1 = __float_as_uint(As[mb + 8 + grp][k0 + q]);
                uint32_t a2 = __float_as_uint(As[mb + grp][k0 + q + 4]);
                uint32_t a3 = __float_as_uint(As[mb + 8 + grp][k0 + q + 4]);
#pragma unroll
                for (int ni = 0; ni < 4; ni++)
                    mma8(acc[mi][ni], a0, a1, a2, a3, b0[ni], b1[ni]);
            }
        }
        __syncthreads();
    }
    float* dst = g_part[12 + blockIdx.z];
#pragma unroll
    for (int mi = 0; mi < 2; mi++) {
        int r0 = m0 + wm * 32 + mi * 16 + grp;
#pragma unroll
        for (int ni = 0; ni < 4; ni++) {
            int c = n0 + wn * 32 + ni * 8 + 2 * q;
            dst[(size_t)r0 * Dn + c]           = acc[mi][ni][0];
            dst[(size_t)r0 * Dn + c + 1]       = acc[mi][ni][1];
            dst[(size_t)(r0 + 8) * Dn + c]     = acc[mi][ni][2];
            dst[(size_t)(r0 + 8) * Dn + c + 1] = acc[mi][ni][3];
        }
    }
}

__global__ void combine_gate_update_kernel(const float* __restrict__ gate_b,
                                           float* __restrict__ u) {
    int i = blockIdx.x * blockDim.x + threadIdx.x;   // float4 index
    if (i < BKD / 4) {
        int n = (i * 4) % Dn;
        float4 s3 = *(const float4*)&g_part[12][i * 4];
        float4 s4 = *(const float4*)&g_part[13][i * 4];
        float4 s5 = *(const float4*)&g_part[14][i * 4];
        float4 s6 = *(const float4*)&g_part[15][i * 4];
        float4 gb = *(const float4*)&gate_b[n];
        float4 uv = *(const float4*)&u[i * 4];
        float4 cv = *(const float4*)&g_c[i * 4];
        float g0 = sigmoidf(s3.x + s4.x + s5.x + s6.x + gb.x);
        float g1 = sigmoidf(s3.y + s4.y + s5.y + s6.y + gb.y);
        float g2 = sigmoidf(s3.z + s4.z + s5.z + s6.z + gb.z);
        float g3 = sigmoidf(s3.w + s4.w + s5.w + s6.w + gb.w);
        float4 o;
        o.x = g0 * uv.x + (1.0f - g0) * cv.x;
        o.y = g1 * uv.y + (1.0f - g1) * cv.y;
        o.z = g2 * uv.z + (1.0f - g2) * cv.z;
        o.w = g3 * uv.w + (1.0f - g3) * cv.w;
        *(float4*)&u[i * 4] = o;
    }
}

__global__ void scatter_kernel(const int* __restrict__ prune, const float* __restrict__ slen,
                               const float* __restrict__ u, float* __restrict__ outAll) {
    int i = blockIdx.x * blockDim.x + threadIdx.x;   // float4 index
    if (i < BKD / 4) {
        int idx = i * 4;
        int d = idx % Dn, bk = idx / Dn, b = bk / Kn, k = bk % Kn;
        if ((float)k < slen[b]) {
            int row = prune[bk];
            *(float4*)&outAll[((size_t)b * Nn + row) * Dn + d] = *(const float4*)&u[idx];
        }
    }
}

// ---------------- driver ---------------------------------------------------
extern "C" void kernel_launch(void* const* d_in, const int* in_sizes, int n_in,
                              void* d_out, int out_size) {
    (void)in_sizes; (void)n_in; (void)out_size;
    const float* all_vecs  = (const float*)d_in[0];
    const float* span_vecs = (const float*)d_in[1];
    const int*   span_beg  = (const int*)  d_in[2];
    const int*   span_end  = (const int*)  d_in[3];
    const float* mask      = (const float*)d_in[4];
    const float* slen      = (const float*)d_in[5];
    const int*   prune     = (const int*)  d_in[6];
    const float* left_w    = (const float*)d_in[7];
    const float* left_b    = (const float*)d_in[8];
    const float* right_w   = (const float*)d_in[9];
    const float* right_b   = (const float*)d_in[10];
    const float* dist_emb  = (const float*)d_in[11];
    const float* out_w     = (const float*)d_in[12];
    const float* out_b     = (const float*)d_in[13];
    const float* A_w       = (const float*)d_in[14];
    const float* B_w       = (const float*)d_in[15];
    const float* gate_w    = (const float*)d_in[16];
    const float* gate_b    = (const float*)d_in[17];

    float* outAll = (float*)d_out;           // [B,N,D]
    float* outU   = outAll + BND;            // [B,K,D]
    float* outS   = outU + BKD;              // [B,K,K,L]

    static int attr_done = 0;
    if (!attr_done) {
        cudaFuncSetAttribute(ctxt_kernel,
                             cudaFuncAttributeMaxDynamicSharedMemorySize, CTXT_SMEM);
        attr_done = 1;
    }

    prep_kernel<<<(2 * Dn * Dn + 255) / 256, 256>>>(out_w, A_w, B_w, left_w, right_w, gate_w);
    copy_init_kernel<<<(BND / 16 + 255) / 256, 256>>>(all_vecs, span_vecs, outAll, outU);

    proj_kernel<<<dim3(4, 8, 3), 256>>>(outU);
    combine_proj_kernel<<<(512 * 512 + 255) / 256, 256>>>(left_b, right_b);
    scores_kernel<<<dim3(2, Kn, Bn), 256>>>(span_beg, span_end, dist_emb, out_b, mask, outS, 0);

    for (int t = 0; t < 3; t++) {
        ctxt_kernel<<<dim3(1, 6, 24), 512, CTXT_SMEM>>>(outU);
        combine_kernel<<<(BKD / 4 + 255) / 256, 256>>>(slen);
        gate_kernel<<<dim3(4, 12, 4), 256>>>(outU);
        combine_gate_update_kernel<<<(BKD / 4 + 255) / 256, 256>>>(gate_b, outU);
        proj_kernel<<<dim3(4, 8, 3), 256>>>(outU);
        combine_proj_kernel<<<(512 * 512 + 255) / 256, 256>>>(left_b, right_b);
        scores_kernel<<<dim3(2, Kn, Bn), 256>>>(span_beg, span_end, dist_emb, out_b, mask,
                                                outS, t == 2 ? 1 : 0);
    }

    scatter_kernel<<<(BKD / 4 + 255) / 256, 256>>>(prune, slen, outU, outAll);
}

// round 17
// speedup vs baseline: 1.2233x; 1.0261x over previous
#include <cuda_runtime.h>
#include <cstdint>

#define Bn 2
#define Nn 2048
#define Kn 256
#define Dn 768
#define Hn 256
#define Ln 64
#define BND (Bn*Nn*Dn)
#define BKD (Bn*Kn*Dn)
#define BKH (Bn*Kn*Hn)
#define BKKL ((size_t)Bn*Kn*Kn*Ln)

// ---------------- scratch (device globals; no allocations allowed) ----------
__device__ float g_left [BKH];
__device__ float g_right[BKH];
__device__ float g_outwT[Hn*Ln];      // [h][l], tf32-rounded
__device__ float g_AwT  [Ln*Dn];      // [l][d], tf32-rounded
__device__ float g_BwT  [Ln*Dn];      // [l][d], tf32-rounded
__device__ float g_lrwT [Dn*512];     // [k][n] (n<256: left, else right), tf32-rounded
__device__ float g_gwT  [2*Dn*Dn];    // [k][n], tf32-rounded gate_w^T
__device__ float g_probs[BKKL];       // sigmoid(score)*mask, tf32-rounded
__device__ float g_part [16][BKD];    // ctxt 0..11; proj reuses 0..5; gate 8..15
__device__ float g_c    [BKD];

__device__ __forceinline__ float sigmoidf(float x) {
    return 1.0f / (1.0f + __expf(-x));
}
__device__ __forceinline__ uint32_t tf32r(float x) {
    uint32_t u; asm("cvt.rna.tf32.f32 %0, %1;" : "=r"(u) : "f"(x)); return u;
}
__device__ __forceinline__ float tf32rf(float x) {
    return __uint_as_float(tf32r(x));
}
__device__ __forceinline__ void mma8(float c[4], uint32_t a0, uint32_t a1, uint32_t a2,
                                     uint32_t a3, uint32_t b0, uint32_t b1) {
    asm("mma.sync.aligned.m16n8k8.row.col.f32.tf32.tf32.f32 "
        "{%0,%1,%2,%3},{%4,%5,%6,%7},{%8,%9},{%0,%1,%2,%3};"
        : "+f"(c[0]), "+f"(c[1]), "+f"(c[2]), "+f"(c[3])
        : "r"(a0), "r"(a1), "r"(a2), "r"(a3), "r"(b0), "r"(b1));
}
__device__ __forceinline__ void cp16(uint32_t daddr, const void* src) {
    asm volatile("cp.async.cg.shared.global [%0], [%1], 16;\n" :: "r"(daddr), "l"(src));
}

// ---------------- prep + init copies (merged) -------------------------------
__global__ void prep_kernel(const float* __restrict__ out_w,
                            const float* __restrict__ A_w,
                            const float* __restrict__ B_w,
                            const float* __restrict__ left_w,
                            const float* __restrict__ right_w,
                            const float* __restrict__ gate_w,
                            const float* __restrict__ all_vecs,
                            const float* __restrict__ span_vecs,
                            float* __restrict__ outAll,
                            float* __restrict__ outU) {
    int i = blockIdx.x * blockDim.x + threadIdx.x;
    if (i < Hn * Ln) { int h = i / Ln, l = i - h * Ln; g_outwT[i] = tf32rf(out_w[l * Hn + h]); }
    if (i < Ln * Dn) { int l = i / Dn, d = i - l * Dn; g_AwT[i] = tf32rf(A_w[d * Ln + l]);
                                                      g_BwT[i] = tf32rf(B_w[d * Ln + l]); }
    if (i < Dn * 512) {
        int k = i >> 9, n = i & 511;
        g_lrwT[i] = tf32rf(n < Hn ? left_w[(size_t)n * Dn + k]
                                  : right_w[(size_t)(n - Hn) * Dn + k]);
    }
    if (i < 2 * Dn * Dn) {
        int k = i / Dn, n = i - k * Dn;
        g_gwT[i] = tf32rf(gate_w[(size_t)n * (2 * Dn) + k]);
    }
    const int stride = BND / 16;
    if (i < stride) {
#pragma unroll
        for (int e = 0; e < 4; e++) {
            int idx = i + e * stride;
            ((float4*)outAll)[idx] = ((const float4*)all_vecs)[idx];
        }
        if (i < BKD / 4) ((float4*)outU)[i] = ((const float4*)span_vecs)[i];
    }
}

// ---------------- proj split-K(6): partials for u @ [left_w|right_w]^T -----
// grid (4, 8, 6): m-tile 128, n-tile 64 over 512 cols, split z covers k [z*128,(z+1)*128)
__global__ __launch_bounds__(256) void proj_kernel(const float* __restrict__ u) {
    __shared__ float As[128][36];
    __shared__ float Bs[32][72];
    const int tid = threadIdx.x;
    const int warp = tid >> 5, lane = tid & 31;
    const int wm = warp & 3, wn = warp >> 2;
    const int grp = lane >> 2, q = lane & 3;
    const int m0 = blockIdx.x * 128, n0 = blockIdx.y * 64;
    const int kBeg = blockIdx.z * 128, kEnd = kBeg + 128;
    const int fm = tid >> 1, fh = tid & 1;
    const int fn = tid & 63, fk = tid >> 6;
    float acc[2][4][4] = {};

    for (int kb = kBeg; kb < kEnd; kb += 32) {
        const float* src = u + (size_t)(m0 + fm) * Dn + kb + fh * 16;
#pragma unroll
        for (int e = 0; e < 4; e++) {
            float4 v = *(const float4*)(src + 4 * e);
            int c = fh * 16 + 4 * e;
            As[fm][c + 0] = tf32rf(v.x); As[fm][c + 1] = tf32rf(v.y);
            As[fm][c + 2] = tf32rf(v.z); As[fm][c + 3] = tf32rf(v.w);
        }
#pragma unroll
        for (int e = 0; e < 8; e++)
            Bs[fk * 8 + e][fn] = g_lrwT[(size_t)(kb + fk * 8 + e) * 512 + n0 + fn];
        __syncthreads();
#pragma unroll
        for (int k0 = 0; k0 < 32; k0 += 8) {
            uint32_t b0[4], b1[4];
#pragma unroll
            for (int ni = 0; ni < 4; ni++) {
                int n = wn * 32 + ni * 8 + grp;
                b0[ni] = __float_as_uint(Bs[k0 + q][n]);
                b1[ni] = __float_as_uint(Bs[k0 + q + 4][n]);
            }
#pragma unroll
            for (int mi = 0; mi < 2; mi++) {
                int mb = wm * 32 + mi * 16;
                uint32_t a0 = __float_as_uint(As[mb + grp][k0 + q]);
                uint32_t a1 = __float_as_uint(As[mb + 8 + grp][k0 + q]);
                uint32_t a2 = __float_as_uint(As[mb + grp][k0 + q + 4]);
                uint32_t a3 = __float_as_uint(As[mb + 8 + grp][k0 + q + 4]);
#pragma unroll
                for (int ni = 0; ni < 4; ni++)
                    mma8(acc[mi][ni], a0, a1, a2, a3, b0[ni], b1[ni]);
            }
        }
        __syncthreads();
    }
    float* dst = g_part[blockIdx.z];
#pragma unroll
    for (int mi = 0; mi < 2; mi++) {
        int r0 = m0 + wm * 32 + mi * 16 + grp;
#pragma unroll
        for (int ni = 0; ni < 4; ni++) {
            int c = n0 + wn * 32 + ni * 8 + 2 * q;
            dst[(size_t)r0 * 512 + c]           = acc[mi][ni][0];
            dst[(size_t)r0 * 512 + c + 1]       = acc[mi][ni][1];
            dst[(size_t)(r0 + 8) * 512 + c]     = acc[mi][ni][2];
            dst[(size_t)(r0 + 8) * 512 + c + 1] = acc[mi][ni][3];
        }
    }
}

__global__ void combine_proj_kernel(const float* __restrict__ left_b,
                                    const float* __restrict__ right_b) {
    int i = blockIdx.x * blockDim.x + threadIdx.x;   // 512*512
    if (i < 512 * 512) {
        int m = i >> 9, n = i & 511;
        float s = g_part[0][i] + g_part[1][i] + g_part[2][i]
                + g_part[3][i] + g_part[4][i] + g_part[5][i];
        if (n < Hn) g_left [(size_t)m * Hn + n]      = s + left_b[n];
        else        g_right[(size_t)m * Hn + n - Hn] = s + right_b[n - Hn];
    }
}

// ---------------- fused pair-scorer + probs (R8 config, measured best) -----
// write_scores=0: probs only.  =1: scores only (final call).
// block = 256 threads = 8 warps (4 m x 2 n), block tile 128j x 64l, K=h(256)
// grid: (2, i=256, b=2)
__global__ __launch_bounds__(256) void scores_kernel(
        const int* __restrict__ span_begin, const int* __restrict__ span_end,
        const float* __restrict__ dist_emb, const float* __restrict__ out_b,
        const float* __restrict__ mask, float* __restrict__ scores,
        int write_scores) {
    __shared__ float As[128][36];
    __shared__ float oS[32][72];
    __shared__ float leftS[Hn];
    const int tid = threadIdx.x;
    const int warp = tid >> 5, lane = tid & 31;
    const int wm = warp & 3, wn = warp >> 2;
    const int grp = lane >> 2, q = lane & 3;
    const int b = blockIdx.z, i = blockIdx.y, j0 = blockIdx.x * 128;
    const int fm = tid >> 1, fh = tid & 1;
    const int fn = tid & 63, fk = tid >> 6;

    leftS[tid] = g_left[(size_t)(b * Kn + i) * Hn + tid];
    int dd = span_begin[b * Kn + j0 + fm] - span_end[b * Kn + i];
    int ad = abs(dd); const int bkt = ad > 63 ? 63 : ad;
    __syncthreads();

    float acc[2][4][4] = {};
    for (int hb = 0; hb < Hn; hb += 32) {
        const float* rsrc = g_right + (size_t)(b * Kn + j0 + fm) * Hn + hb + fh * 16;
        const float* dsrc = dist_emb + (size_t)bkt * Hn + hb + fh * 16;
#pragma unroll
        for (int e = 0; e < 4; e++) {
            float4 rv = *(const float4*)(rsrc + 4 * e);
            float4 dv = *(const float4*)(dsrc + 4 * e);
            int c = fh * 16 + 4 * e;
            float4 lv = *(const float4*)(&leftS[hb + c]);
            As[fm][c + 0] = tf32rf(fmaxf(lv.x + rv.x + dv.x, 0.f));
            As[fm][c + 1] = tf32rf(fmaxf(lv.y + rv.y + dv.y, 0.f));
            As[fm][c + 2] = tf32rf(fmaxf(lv.z + rv.z + dv.z, 0.f));
            As[fm][c + 3] = tf32rf(fmaxf(lv.w + rv.w + dv.w, 0.f));
        }
#pragma unroll
        for (int e = 0; e < 8; e++)
            oS[fk * 8 + e][fn] = g_outwT[(size_t)(hb + fk * 8 + e) * Ln + fn];
        __syncthreads();
#pragma unroll
        for (int k0 = 0; k0 < 32; k0 += 8) {
            uint32_t b0[4], b1[4];
#pragma unroll
            for (int ni = 0; ni < 4; ni++) {
                int n = wn * 32 + ni * 8 + grp;
                b0[ni] = __float_as_uint(oS[k0 + q][n]);
                b1[ni] = __float_as_uint(oS[k0 + q + 4][n]);
            }
#pragma unroll
            for (int mi = 0; mi < 2; mi++) {
                int mb = wm * 32 + mi * 16;
                uint32_t a0 = __float_as_uint(As[mb + grp][k0 + q]);
                uint32_t a1 = __float_as_uint(As[mb + 8 + grp][k0 + q]);
                uint32_t a2 = __float_as_uint(As[mb + grp][k0 + q + 4]);
                uint32_t a3 = __float_as_uint(As[mb + 8 + grp][k0 + q + 4]);
#pragma unroll
                for (int ni = 0; ni < 4; ni++)
                    mma8(acc[mi][ni], a0, a1, a2, a3, b0[ni], b1[ni]);
            }
        }
        __syncthreads();
    }
    float* scRow = scores + (size_t)(b * Kn + i) * (Kn * Ln);
    float* prRow = g_probs + (size_t)(b * Kn + i) * (Kn * Ln);
    const float* mkRow = mask + (size_t)(b * Kn + i) * Kn;
#pragma unroll
    for (int mi = 0; mi < 2; mi++) {
        int j0l = wm * 32 + mi * 16 + grp;
        float mk0 = mkRow[j0 + j0l], mk1 = mkRow[j0 + j0l + 8];
#pragma unroll
        for (int ni = 0; ni < 4; ni++) {
            int c = wn * 32 + ni * 8 + 2 * q;
#pragma unroll
            for (int e = 0; e < 2; e++) {
                float s0 = acc[mi][ni][e]     + out_b[c + e];
                float s1 = acc[mi][ni][2 + e] + out_b[c + e];
                if (write_scores) {
                    scRow[(size_t)(j0 + j0l) * Ln + c + e]     = s0;
                    scRow[(size_t)(j0 + j0l + 8) * Ln + c + e] = s1;
                } else {
                    prRow[(size_t)(j0 + j0l) * Ln + c + e]     = tf32rf(sigmoidf(s0) * mk0);
                    prRow[(size_t)(j0 + j0l + 8) * Ln + c + e] = tf32rf(sigmoidf(s1) * mk1);
                }
            }
        }
    }
}

// ---------------- context GEMMs: wide d-tile (128), 512 threads ------------
// block = 512 threads = 16 warps (4m x 4n), block tile 256m x 128d.
// 6 UNEVEN k-splits (86,86,85,85,85,85 chunks of 512).
// grid: (1, d-tile=6, z = b*12 + mode*6 + split) = 144 blocks = one wave @1/SM
#define CTXT_SMEM ((2 * 256 * 36 + 64 * 136) * 4)
__global__ __launch_bounds__(512, 1) void ctxt_kernel(const float* __restrict__ u) {
    extern __shared__ float dsm[];
    float* AsBase = dsm;                   // 2 * 9216
    float* wS     = dsm + 2 * 256 * 36;    // 64 * 136
    const int tid = threadIdx.x;
    const int warp = tid >> 5, lane = tid & 31;
    const int wm = warp & 3, wn = warp >> 2;      // wn 0..3
    const int grp = lane >> 2, q = lane & 3;
    const int z = blockIdx.z;
    const int b = z / 12, r12 = z % 12, mode = r12 / 6, split = r12 % 6;
    const int d0 = blockIdx.y * 128;
    const float* wT = (mode == 0) ? g_AwT : g_BwT;
    const float* probsB = g_probs + (size_t)b * Kn * Kn * Ln;
    const float* uB     = u       + (size_t)b * Kn * Dn;
    const int arow = tid >> 3, aq = tid & 7;

    int cn[4], dcol[4];
#pragma unroll
    for (int ni = 0; ni < 4; ni++) {
        cn[ni]   = wn * 32 + ni * 8 + grp;
        dcol[ni] = d0 + cn[ni];
    }

    {
        int l = tid >> 3;
#pragma unroll
        for (int e = 0; e < 4; e++) {
            int c = aq * 16 + 4 * e;
            float4 v = *(const float4*)&wT[(size_t)l * Dn + d0 + c];
            wS[l * 136 + c + 0] = v.x; wS[l * 136 + c + 1] = v.y;
            wS[l * 136 + c + 2] = v.z; wS[l * 136 + c + 3] = v.w;
        }
    }

    const int begChunk = split * 85 + (split < 2 ? split : 2);
    const int NC       = 85 + (split < 2 ? 1 : 0);
    const int rBeg     = begChunk * 32;

    auto issueA = [&](int c, int buf) {
        int rb = rBeg + c * 32;
        int other = rb >> 6, l0 = rb & 63;
        float* dstBase = AsBase + buf * 9216;
#pragma unroll
        for (int p = 0; p < 4; p++) {
            int m = p * 64 + arow;
            const float* src = (mode == 0)
                ? &probsB[((size_t)other * Kn + m) * Ln + l0 + aq * 4]
                : &probsB[((size_t)m * Kn + other) * Ln + l0 + aq * 4];
            uint32_t daddr = (uint32_t)__cvta_generic_to_shared(dstBase + m * 36 + aq * 4);
            cp16(daddr, src);
        }
    };

    issueA(0, 0);
    asm volatile("cp.async.commit_group;\n");
    __syncthreads();

    float acc[4][4][4] = {};
    float uval[4], unext[4];
    {
        int o0 = rBeg >> 6;
#pragma unroll
        for (int ni = 0; ni < 4; ni++) uval[ni] = uB[(size_t)o0 * Dn + dcol[ni]];
    }

    for (int c = 0; c < NC; c++) {
        if (c + 1 < NC) {
            issueA(c + 1, (c + 1) & 1);
            int on = (rBeg + (c + 1) * 32) >> 6;
#pragma unroll
            for (int ni = 0; ni < 4; ni++) unext[ni] = uB[(size_t)on * Dn + dcol[ni]];
        }
        asm volatile("cp.async.commit_group;\n");
        if (c + 1 < NC) asm volatile("cp.async.wait_group 1;\n");
        else            asm volatile("cp.async.wait_group 0;\n");
        __syncthreads();

        const float* AsBuf = AsBase + (c & 1) * 9216;
        const int l0 = (rBeg + c * 32) & 63;
#pragma unroll
        for (int k0 = 0; k0 < 32; k0 += 8) {
            uint32_t b0[4], b1[4];
#pragma unroll
            for (int ni = 0; ni < 4; ni++) {
                float w0 = wS[(l0 + k0 + q) * 136 + cn[ni]];
                float w1 = wS[(l0 + k0 + q + 4) * 136 + cn[ni]];
                b0[ni] = __float_as_uint(uval[ni] * w0);   // mma reads tf32 bits (RZ)
                b1[ni] = __float_as_uint(uval[ni] * w1);
            }
#pragma unroll
            for (int mi = 0; mi < 4; mi++) {
                int mb = wm * 64 + mi * 16;
                uint32_t a0 = __float_as_uint(AsBuf[(mb + grp) * 36 + k0 + q]);
                uint32_t a1 = __float_as_uint(AsBuf[(mb + 8 + grp) * 36 + k0 + q]);
                uint32_t a2 = __float_as_uint(AsBuf[(mb + grp) * 36 + k0 + q + 4]);
                uint32_t a3 = __float_as_uint(AsBuf[(mb + 8 + grp) * 36 + k0 + q + 4]);
#pragma unroll
                for (int ni = 0; ni < 4; ni++)
                    mma8(acc[mi][ni], a0, a1, a2, a3, b0[ni], b1[ni]);
            }
        }
        __syncthreads();
#pragma unroll
        for (int ni = 0; ni < 4; ni++) uval[ni] = unext[ni];
    }

    float* dst = g_part[mode * 6 + split];
#pragma unroll
    for (int mi = 0; mi < 4; mi++) {
        int row = wm * 64 + mi * 16 + grp;
#pragma unroll
        for (int ni = 0; ni < 4; ni++) {
            int c = d0 + wn * 32 + ni * 8 + 2 * q;
            *(float2*)&dst[((size_t)b * Kn + row) * Dn + c] =
                make_float2(acc[mi][ni][0], acc[mi][ni][1]);
            *(float2*)&dst[((size_t)b * Kn + row + 8) * Dn + c] =
                make_float2(acc[mi][ni][2], acc[mi][ni][3]);
        }
    }
}

__global__ void combine_kernel(const float* __restrict__ slen) {
    int i = blockIdx.x * blockDim.x + threadIdx.x;   // float4 index
    if (i < BKD / 4) {
        int b = (i * 4) / (Kn * Dn);
        float4 s = make_float4(0.f, 0.f, 0.f, 0.f);
#pragma unroll
        for (int p = 0; p < 12; p++) {
            float4 v = *(const float4*)&g_part[p][i * 4];
            s.x += v.x; s.y += v.y; s.z += v.z; s.w += v.w;
        }
        float inv = 1.0f / slen[b];
        s.x *= inv; s.y *= inv; s.z *= inv; s.w *= inv;
        *(float4*)&g_c[i * 4] = s;
    }
}

// ---------------- gate split-K(8): partials of [u|c] @ gate_w^T ------------
// grid (4, 12, 8): split z covers k [z*192,(z+1)*192); partials -> slots 8..15
__global__ __launch_bounds__(256) void gate_kernel(const float* __restrict__ u) {
    __shared__ float As[128][36];
    __shared__ float Bs[32][72];
    const int tid = threadIdx.x;
    const int warp = tid >> 5, lane = tid & 31;
    const int wm = warp & 3, wn = warp >> 2;
    const int grp = lane >> 2, q = lane & 3;
    const int m0 = blockIdx.x * 128, n0 = blockIdx.y * 64;
    const int kBeg = blockIdx.z * 192, kEnd = kBeg + 192;
    const int fm = tid >> 1, fh = tid & 1;
    const int fn = tid & 63, fk = tid >> 6;
    float acc[2][4][4] = {};

    for (int kb = kBeg; kb < kEnd; kb += 32) {
        const float* src = (kb < Dn)
            ? u   + (size_t)(m0 + fm) * Dn + kb + fh * 16
            : g_c + (size_t)(m0 + fm) * Dn + (kb - Dn) + fh * 16;
#pragma unroll
        for (int e = 0; e < 4; e++) {
            float4 v = *(const float4*)(src + 4 * e);
            int c = fh * 16 + 4 * e;
            As[fm][c + 0] = tf32rf(v.x); As[fm][c + 1] = tf32rf(v.y);
            As[fm][c + 2] = tf32rf(v.z); As[fm][c + 3] = tf32rf(v.w);
        }
#pragma unroll
        for (int e = 0; e < 8; e++)
            Bs[fk * 8 + e][fn] = g_gwT[(size_t)(kb + fk * 8 + e) * Dn + n0 + fn];
        __syncthreads();
#pragma unroll
        for (int k0 = 0; k0 < 32; k0 += 8) {
            uint32_t b0[4], b1[4];
#pragma unroll
            for (int ni = 0; ni < 4; ni++) {
                int n = wn * 32 + ni * 8 + grp;
                b0[ni] = __float_as_uint(Bs[k0 + q][n]);
                b1[ni] = __float_as_uint(Bs[k0 + q + 4][n]);
            }
#pragma unroll
            for (int mi = 0; mi < 2; mi++) {
                int mb = wm * 32 + mi * 16;
                uint32_t a0 = __float_as_uint(As[mb + grp][k0 + q]);
                uint32_t a1 = __float_as_uint(As[mb + 8 + grp][k0 + q]);
                uint32_t a2 = __float_as_uint(As[mb + grp][k0 + q + 4]);
                uint32_t a3 = __float_as_uint(As[mb + 8 + grp][k0 + q + 4]);
#pragma unroll
                for (int ni = 0; ni < 4; ni++)
                    mma8(acc[mi][ni], a0, a1, a2, a3, b0[ni], b1[ni]);
            }
        }
        __syncthreads();
    }
    float* dst = g_part[8 + blockIdx.z];
#pragma unroll
    for (int mi = 0; mi < 2; mi++) {
        int r0 = m0 + wm * 32 + mi * 16 + grp;
#pragma unroll
        for (int ni = 0; ni < 4; ni++) {
            int c = n0 + wn * 32 + ni * 8 + 2 * q;
            dst[(size_t)r0 * Dn + c]           = acc[mi][ni][0];
            dst[(size_t)r0 * Dn + c + 1]       = acc[mi][ni][1];
            dst[(size_t)(r0 + 8) * Dn + c]     = acc[mi][ni][2];
            dst[(size_t)(r0 + 8) * Dn + c + 1] = acc[mi][ni][3];
        }
    }
}

// combine gate partials + gated update; optionally fused final scatter
__global__ void combine_gate_update_kernel(const float* __restrict__ gate_b,
                                           float* __restrict__ u,
                                           const int* __restrict__ prune,
                                           const float* __restrict__ slen,
                                           float* __restrict__ outAll,
                                           int do_scatter) {
    int i = blockIdx.x * blockDim.x + threadIdx.x;   // float4 index
    if (i < BKD / 4) {
        int idx = i * 4;
        int n = idx % Dn;
        float4 s = make_float4(0.f, 0.f, 0.f, 0.f);
#pragma unroll
        for (int p = 8; p < 16; p++) {
            float4 v = *(const float4*)&g_part[p][idx];
            s.x += v.x; s.y += v.y; s.z += v.z; s.w += v.w;
        }
        float4 gb = *(const float4*)&gate_b[n];
        float4 uv = *(const float4*)&u[idx];
        float4 cv = *(const float4*)&g_c[idx];
        float g0 = sigmoidf(s.x + gb.x);
        float g1 = sigmoidf(s.y + gb.y);
        float g2 = sigmoidf(s.z + gb.z);
        float g3 = sigmoidf(s.w + gb.w);
        float4 o;
        o.x = g0 * uv.x + (1.0f - g0) * cv.x;
        o.y = g1 * uv.y + (1.0f - g1) * cv.y;
        o.z = g2 * uv.z + (1.0f - g2) * cv.z;
        o.w = g3 * uv.w + (1.0f - g3) * cv.w;
        *(float4*)&u[idx] = o;
        if (do_scatter) {
            int bk = idx / Dn, b = bk / Kn, k = bk % Kn;
            if ((float)k < slen[b]) {
                int row = prune[bk];
                *(float4*)&outAll[((size_t)b * Nn + row) * Dn + n] = o;
            }
        }
    }
}

// ---------------- driver ---------------------------------------------------
extern "C" void kernel_launch(void* const* d_in, const int* in_sizes, int n_in,
                              void* d_out, int out_size) {
    (void)in_sizes; (void)n_in; (void)out_size;
    const float* all_vecs  = (const float*)d_in[0];
    const float* span_vecs = (const float*)d_in[1];
    const int*   span_beg  = (const int*)  d_in[2];
    const int*   span_end  = (const int*)  d_in[3];
    const float* mask      = (const float*)d_in[4];
    const float* slen      = (const float*)d_in[5];
    const int*   prune     = (const int*)  d_in[6];
    const float* left_w    = (const float*)d_in[7];
    const float* left_b    = (const float*)d_in[8];
    const float* right_w   = (const float*)d_in[9];
    const float* right_b   = (const float*)d_in[10];
    const float* dist_emb  = (const float*)d_in[11];
    const float* out_w     = (const float*)d_in[12];
    const float* out_b     = (const float*)d_in[13];
    const float* A_w       = (const float*)d_in[14];
    const float* B_w       = (const float*)d_in[15];
    const float* gate_w    = (const float*)d_in[16];
    const float* gate_b    = (const float*)d_in[17];

    float* outAll = (float*)d_out;           // [B,N,D]
    float* outU   = outAll + BND;            // [B,K,D]
    float* outS   = outU + BKD;              // [B,K,K,L]

    static int attr_done = 0;
    if (!attr_done) {
        cudaFuncSetAttribute(ctxt_kernel,
                             cudaFuncAttributeMaxDynamicSharedMemorySize, CTXT_SMEM);
        attr_done = 1;
    }

    prep_kernel<<<(2 * Dn * Dn + 255) / 256, 256>>>(out_w, A_w, B_w, left_w, right_w, gate_w,
                                                    all_vecs, span_vecs, outAll, outU);

    proj_kernel<<<dim3(4, 8, 6), 256>>>(outU);
    combine_proj_kernel<<<(512 * 512 + 255) / 256, 256>>>(left_b, right_b);
    scores_kernel<<<dim3(2, Kn, Bn), 256>>>(span_beg, span_end, dist_emb, out_b, mask, outS, 0);

    for (int t = 0; t < 3; t++) {
        ctxt_kernel<<<dim3(1, 6, 24), 512, CTXT_SMEM>>>(outU);
        combine_kernel<<<(BKD / 4 + 255) / 256, 256>>>(slen);
        gate_kernel<<<dim3(4, 12, 8), 256>>>(outU);
        combine_gate_update_kernel<<<(BKD / 4 + 255) / 256, 256>>>(
            gate_b, outU, prune, slen, outAll, t == 2 ? 1 : 0);
        proj_kernel<<<dim3(4, 8, 6), 256>>>(outU);
        combine_proj_kernel<<<(512 * 512 + 255) / 256, 256>>>(left_b, right_b);
        scores_kernel<<<dim3(2, Kn, Bn), 256>>>(span_beg, span_end, dist_emb, out_b, mask,
                                                outS, t == 2 ? 1 : 0);
    }
}